// round 1
// baseline (speedup 1.0000x reference)
#include <cuda_runtime.h>
#include <math.h>

#define NWIN 512
#define NTOK 256
#define CH   96
#define NH   3
#define HD   32
#define HID  384
#define TPB  256

// Scratch (device globals; no allocation allowed in kernel_launch)
__device__ float g_t[NWIN * CH * NTOK];          // residual stream, [w][c][t]
__device__ float g_qkv[NWIN * 3 * NH * HD * NTOK]; // [w][qkv][h][d][t]
__device__ float g_o[NWIN * CH * NTOK];          // attn out, [w][c][t]
__device__ float g_m[NWIN * HID * NTOK];         // gelu(fc1), [w][f][t]
__device__ float g_bias[NH * NTOK * NTOK];       // [h][m][n] (transposed for coalesced n reads)

// ---------------------------------------------------------------------------
// K0: gather relative-position bias into [h][m][n]
// ---------------------------------------------------------------------------
__global__ void bias_kernel(const float* __restrict__ bias_table) {
    int m = blockIdx.x & 255;
    int h = blockIdx.x >> 8;
    int n = threadIdx.x;
    int dy = (n >> 4) - (m >> 4);
    int dx = (n & 15) - (m & 15);
    int idx = (dy + 15) * 31 + (dx + 15);
    g_bias[(h * NTOK + m) * NTOK + n] = bias_table[idx * NH + h];
}

// ---------------------------------------------------------------------------
// K1: window partition + LN1 + QKV GEMM (one CTA per window, one thread/token)
// ---------------------------------------------------------------------------
__global__ void qkv_kernel(const float* __restrict__ x,
                           const float* __restrict__ qkv_w,
                           const float* __restrict__ qkv_b,
                           const float* __restrict__ ln_g,
                           const float* __restrict__ ln_b) {
    extern __shared__ float sm[];
    float* h_s = sm;              // [CH][NTOK]
    float* w_s = sm + CH * NTOK;  // [32][CH]
    int w = blockIdx.x, t = threadIdx.x;
    int b = w >> 8, hb = (w >> 4) & 15, wb = w & 15;
    int d = t >> 6, i = (t >> 3) & 7, j = t & 7;
    const float* xp = x + ((b * CH) * 4 + d) * 16384 + (hb * 8 + i) * 128 + (wb * 8 + j);

    float sum = 0.f, sq = 0.f;
    #pragma unroll 4
    for (int c = 0; c < CH; c++) {
        float v = xp[c * 65536];
        sum += v; sq += v * v;
        h_s[c * NTOK + t] = v;
        g_t[(w * CH + c) * NTOK + t] = v;   // raw residual
    }
    float mean = sum * (1.f / CH);
    float rstd = rsqrtf(sq * (1.f / CH) - mean * mean + 1e-5f);
    #pragma unroll 4
    for (int c = 0; c < CH; c++)
        h_s[c * NTOK + t] = (h_s[c * NTOK + t] - mean) * rstd * ln_g[c] + ln_b[c];
    // columns of h_s are thread-private; syncs only guard weight tiles

    for (int tile = 0; tile < 9; tile++) {
        __syncthreads();
        for (int idx = t; idx < 32 * CH; idx += TPB)
            w_s[idx] = qkv_w[tile * 32 * CH + idx];
        __syncthreads();
        float acc[32];
        #pragma unroll
        for (int oc = 0; oc < 32; oc++) acc[oc] = 0.f;
        for (int c = 0; c < CH; c += 4) {
            float h0 = h_s[(c + 0) * NTOK + t], h1 = h_s[(c + 1) * NTOK + t];
            float h2 = h_s[(c + 2) * NTOK + t], h3 = h_s[(c + 3) * NTOK + t];
            #pragma unroll
            for (int oc = 0; oc < 32; oc++) {
                float4 wv = *(const float4*)&w_s[oc * CH + c];
                acc[oc] += h0 * wv.x + h1 * wv.y + h2 * wv.z + h3 * wv.w;
            }
        }
        int qkvi = tile / 3, hh = tile % 3;
        float scale = (qkvi == 0) ? 0.17677669529663687f : 1.f;  // hd^-0.5 on q
        int base = ((w * 3 + qkvi) * NH + hh) * HD * NTOK;
        #pragma unroll
        for (int oc = 0; oc < 32; oc++)
            g_qkv[base + oc * NTOK + t] = (acc[oc] + qkv_b[tile * 32 + oc]) * scale;
    }
}

// ---------------------------------------------------------------------------
// K2: window attention, one CTA per (window, head), online softmax per token
// ---------------------------------------------------------------------------
__global__ void attn_kernel() {
    extern __shared__ float sm[];
    float* k_s = sm;              // [m][36] padded
    float* v_s = sm + NTOK * 36;  // [m][36] padded
    int bx = blockIdx.x;
    int w = bx / 3, h = bx % 3;
    int t = threadIdx.x;
    int qb = ((w * 3 + 0) * NH + h) * HD * NTOK;
    int kb = ((w * 3 + 1) * NH + h) * HD * NTOK;
    int vb = ((w * 3 + 2) * NH + h) * HD * NTOK;

    for (int idx = t; idx < HD * NTOK; idx += TPB) {
        int d = idx >> 8, m = idx & 255;
        k_s[m * 36 + d] = g_qkv[kb + idx];
        v_s[m * 36 + d] = g_qkv[vb + idx];
    }
    float qr[32];
    #pragma unroll
    for (int d = 0; d < 32; d++) qr[d] = g_qkv[qb + d * NTOK + t];
    __syncthreads();

    const float* brow = g_bias + h * NTOK * NTOK + t;  // bias[h][m][n=t]
    float maxv = -1e30f, ssum = 0.f;
    float acc[32];
    #pragma unroll
    for (int d = 0; d < 32; d++) acc[d] = 0.f;

    for (int m = 0; m < NTOK; m++) {
        float s = brow[m * NTOK];
        const float4* kr = (const float4*)&k_s[m * 36];
        #pragma unroll
        for (int d = 0; d < 8; d++) {
            float4 kv = kr[d];
            s += qr[4*d] * kv.x + qr[4*d+1] * kv.y + qr[4*d+2] * kv.z + qr[4*d+3] * kv.w;
        }
        const float4* vr = (const float4*)&v_s[m * 36];
        if (s <= maxv) {
            float p = __expf(s - maxv);
            ssum += p;
            #pragma unroll
            for (int d = 0; d < 8; d++) {
                float4 vv = vr[d];
                acc[4*d]   += p * vv.x; acc[4*d+1] += p * vv.y;
                acc[4*d+2] += p * vv.z; acc[4*d+3] += p * vv.w;
            }
        } else {  // new max: rescale (rare after first few iters)
            float corr = __expf(maxv - s);
            ssum = ssum * corr + 1.f;
            #pragma unroll
            for (int d = 0; d < 8; d++) {
                float4 vv = vr[d];
                acc[4*d]   = acc[4*d]   * corr + vv.x;
                acc[4*d+1] = acc[4*d+1] * corr + vv.y;
                acc[4*d+2] = acc[4*d+2] * corr + vv.z;
                acc[4*d+3] = acc[4*d+3] * corr + vv.w;
            }
            maxv = s;
        }
    }
    float rinv = 1.f / ssum;
    int ob = (w * CH + h * HD) * NTOK;
    #pragma unroll
    for (int d = 0; d < 32; d++)
        g_o[ob + d * NTOK + t] = acc[d] * rinv;
}

// ---------------------------------------------------------------------------
// K3: proj + residual (updates g_t in place)
// ---------------------------------------------------------------------------
__global__ void proj_kernel(const float* __restrict__ proj_w,
                            const float* __restrict__ proj_b) {
    extern __shared__ float sm[];
    float* o_s = sm;              // [CH][NTOK]
    float* w_s = sm + CH * NTOK;  // [CH][CH]
    int w = blockIdx.x, t = threadIdx.x;
    int ob = w * CH * NTOK;
    for (int idx = t; idx < CH * NTOK; idx += TPB) o_s[idx] = g_o[ob + idx];
    for (int idx = t; idx < CH * CH; idx += TPB) w_s[idx] = proj_w[idx];
    __syncthreads();

    for (int chunk = 0; chunk < 3; chunk++) {
        float acc[32];
        #pragma unroll
        for (int oc = 0; oc < 32; oc++) acc[oc] = 0.f;
        for (int c = 0; c < CH; c += 4) {
            float o0 = o_s[(c + 0) * NTOK + t], o1 = o_s[(c + 1) * NTOK + t];
            float o2 = o_s[(c + 2) * NTOK + t], o3 = o_s[(c + 3) * NTOK + t];
            #pragma unroll
            for (int oc = 0; oc < 32; oc++) {
                float4 wv = *(const float4*)&w_s[(chunk * 32 + oc) * CH + c];
                acc[oc] += o0 * wv.x + o1 * wv.y + o2 * wv.z + o3 * wv.w;
            }
        }
        #pragma unroll
        for (int oc = 0; oc < 32; oc++) {
            int gc = chunk * 32 + oc;
            g_t[(w * CH + gc) * NTOK + t] += acc[oc] + proj_b[gc];
        }
    }
}

// ---------------------------------------------------------------------------
// K4: LN2 + fc1 + exact GELU
// ---------------------------------------------------------------------------
__global__ void mlp1_kernel(const float* __restrict__ ln_g,
                            const float* __restrict__ ln_b,
                            const float* __restrict__ fc1_w,
                            const float* __restrict__ fc1_b) {
    extern __shared__ float sm[];
    float* t_s = sm;              // [CH][NTOK]
    float* w_s = sm + CH * NTOK;  // [32][CH]
    int w = blockIdx.x, t = threadIdx.x;
    int tb = w * CH * NTOK;
    for (int idx = t; idx < CH * NTOK; idx += TPB) t_s[idx] = g_t[tb + idx];
    __syncthreads();

    float sum = 0.f, sq = 0.f;
    #pragma unroll 4
    for (int c = 0; c < CH; c++) {
        float v = t_s[c * NTOK + t];
        sum += v; sq += v * v;
    }
    float mean = sum * (1.f / CH);
    float rstd = rsqrtf(sq * (1.f / CH) - mean * mean + 1e-5f);
    #pragma unroll 4
    for (int c = 0; c < CH; c++)
        t_s[c * NTOK + t] = (t_s[c * NTOK + t] - mean) * rstd * ln_g[c] + ln_b[c];

    for (int tile = 0; tile < 12; tile++) {
        __syncthreads();
        for (int idx = t; idx < 32 * CH; idx += TPB)
            w_s[idx] = fc1_w[tile * 32 * CH + idx];
        __syncthreads();
        float acc[32];
        #pragma unroll
        for (int oc = 0; oc < 32; oc++) acc[oc] = 0.f;
        for (int c = 0; c < CH; c += 4) {
            float h0 = t_s[(c + 0) * NTOK + t], h1 = t_s[(c + 1) * NTOK + t];
            float h2 = t_s[(c + 2) * NTOK + t], h3 = t_s[(c + 3) * NTOK + t];
            #pragma unroll
            for (int oc = 0; oc < 32; oc++) {
                float4 wv = *(const float4*)&w_s[oc * CH + c];
                acc[oc] += h0 * wv.x + h1 * wv.y + h2 * wv.z + h3 * wv.w;
            }
        }
        #pragma unroll
        for (int oc = 0; oc < 32; oc++) {
            float vv = acc[oc] + fc1_b[tile * 32 + oc];
            float ge = 0.5f * vv * (1.f + erff(vv * 0.70710678118654752f));
            g_m[(w * HID + tile * 32 + oc) * NTOK + t] = ge;
        }
    }
}

// ---------------------------------------------------------------------------
// K5: fc2 + residual -> out (B_,N,C) row-major
// ---------------------------------------------------------------------------
__global__ void mlp2_kernel(const float* __restrict__ fc2_w,
                            const float* __restrict__ fc2_b,
                            float* __restrict__ out) {
    extern __shared__ float sm[];
    float* m_s = sm;              // [CH k-tile][NTOK]
    float* w_s = sm + CH * NTOK;  // [CH out][CH k-tile]
    int w = blockIdx.x, t = threadIdx.x;
    float acc[96];
    #pragma unroll
    for (int oc = 0; oc < 96; oc++) acc[oc] = 0.f;

    for (int kt = 0; kt < 4; kt++) {
        __syncthreads();
        int mb = (w * HID + kt * CH) * NTOK;
        for (int idx = t; idx < CH * NTOK; idx += TPB) m_s[idx] = g_m[mb + idx];
        for (int idx = t; idx < CH * CH; idx += TPB) {
            int oc = idx / CH, kc = idx - oc * CH;
            w_s[idx] = fc2_w[oc * HID + kt * CH + kc];
        }
        __syncthreads();
        for (int c = 0; c < CH; c += 4) {
            float m0 = m_s[(c + 0) * NTOK + t], m1 = m_s[(c + 1) * NTOK + t];
            float m2 = m_s[(c + 2) * NTOK + t], m3 = m_s[(c + 3) * NTOK + t];
            #pragma unroll
            for (int oc = 0; oc < 96; oc++) {
                float4 wv = *(const float4*)&w_s[oc * CH + c];
                acc[oc] += m0 * wv.x + m1 * wv.y + m2 * wv.z + m3 * wv.w;
            }
        }
    }
    int tbb = w * CH * NTOK;
    float* op = out + (w * NTOK + t) * CH;
    #pragma unroll
    for (int oc = 0; oc < 96; oc += 4) {
        float4 r;
        r.x = acc[oc + 0] + fc2_b[oc + 0] + g_t[tbb + (oc + 0) * NTOK + t];
        r.y = acc[oc + 1] + fc2_b[oc + 1] + g_t[tbb + (oc + 1) * NTOK + t];
        r.z = acc[oc + 2] + fc2_b[oc + 2] + g_t[tbb + (oc + 2) * NTOK + t];
        r.w = acc[oc + 3] + fc2_b[oc + 3] + g_t[tbb + (oc + 3) * NTOK + t];
        *(float4*)&op[oc] = r;
    }
}

// ---------------------------------------------------------------------------
extern "C" void kernel_launch(void* const* d_in, const int* in_sizes, int n_in,
                              void* d_out, int out_size) {
    (void)in_sizes; (void)n_in; (void)out_size;
    const float* x      = (const float*)d_in[0];
    const float* qkv_w  = (const float*)d_in[1];
    const float* qkv_b  = (const float*)d_in[2];
    const float* proj_w = (const float*)d_in[3];
    const float* proj_b = (const float*)d_in[4];
    const float* btab   = (const float*)d_in[5];
    const float* ln1_g  = (const float*)d_in[6];
    const float* ln1_b  = (const float*)d_in[7];
    const float* ln2_g  = (const float*)d_in[8];
    const float* ln2_b  = (const float*)d_in[9];
    const float* fc1_w  = (const float*)d_in[10];
    const float* fc1_b  = (const float*)d_in[11];
    const float* fc2_w  = (const float*)d_in[12];
    const float* fc2_b  = (const float*)d_in[13];
    float* out = (float*)d_out;

    const int smem_qkv  = (CH * NTOK + 32 * CH) * 4;   // 110592 B
    const int smem_attn = 2 * NTOK * 36 * 4;           //  73728 B
    const int smem_proj = (CH * NTOK + CH * CH) * 4;   // 135168 B
    const int smem_mlp1 = (CH * NTOK + 32 * CH) * 4;   // 110592 B
    const int smem_mlp2 = (CH * NTOK + CH * CH) * 4;   // 135168 B
    cudaFuncSetAttribute(qkv_kernel,  cudaFuncAttributeMaxDynamicSharedMemorySize, smem_qkv);
    cudaFuncSetAttribute(attn_kernel, cudaFuncAttributeMaxDynamicSharedMemorySize, smem_attn);
    cudaFuncSetAttribute(proj_kernel, cudaFuncAttributeMaxDynamicSharedMemorySize, smem_proj);
    cudaFuncSetAttribute(mlp1_kernel, cudaFuncAttributeMaxDynamicSharedMemorySize, smem_mlp1);
    cudaFuncSetAttribute(mlp2_kernel, cudaFuncAttributeMaxDynamicSharedMemorySize, smem_mlp2);

    bias_kernel<<<NH * NTOK, NTOK>>>(btab);
    qkv_kernel<<<NWIN, TPB, smem_qkv>>>(x, qkv_w, qkv_b, ln1_g, ln1_b);
    attn_kernel<<<NWIN * NH, TPB, smem_attn>>>();
    proj_kernel<<<NWIN, TPB, smem_proj>>>(proj_w, proj_b);
    mlp1_kernel<<<NWIN, TPB, smem_mlp1>>>(ln2_g, ln2_b, fc1_w, fc1_b);
    mlp2_kernel<<<NWIN, TPB, smem_mlp2>>>(fc2_w, fc2_b, out);
}

// round 2
// speedup vs baseline: 1.5731x; 1.5731x over previous
#include <cuda_runtime.h>
#include <math.h>
#include <stdint.h>

#define NWIN 512
#define NTOK 256
#define CH   96
#define NH   3
#define HD   32
#define HID  384
#define LDA  100   // smem row stride (words) -> conflict-free mma fragment loads

// Scratch (device globals)
__device__ float    g_t[(size_t)NWIN * NTOK * CH];        // residual, [w][t][c]
__device__ float    g_qkv[(size_t)NWIN * 3 * NH * NTOK * HD]; // [w][qkv][h][t][d]
__device__ float    g_o[(size_t)NWIN * NTOK * CH];        // attn out, [w][t][c]
__device__ uint32_t g_m[(size_t)NWIN * NTOK * HID];       // gelu(fc1) as tf32 bits, [w][t][f]
__device__ float    g_bias[NH * NTOK * NTOK];             // [h][m][n]

// ---------------------------------------------------------------------------
__device__ __forceinline__ uint32_t f2tf(float f) {
    uint32_t u;
    asm("cvt.rna.tf32.f32 %0, %1;" : "=r"(u) : "f"(f));
    return u;
}

__device__ __forceinline__ void mma8(float* c, const uint32_t* a, uint32_t b0, uint32_t b1) {
    asm("mma.sync.aligned.m16n8k8.row.col.f32.tf32.tf32.f32 "
        "{%0,%1,%2,%3},{%4,%5,%6,%7},{%8,%9},{%0,%1,%2,%3};"
        : "+f"(c[0]), "+f"(c[1]), "+f"(c[2]), "+f"(c[3])
        : "r"(a[0]), "r"(a[1]), "r"(a[2]), "r"(a[3]), "r"(b0), "r"(b1));
}

// Warp computes a 32-token x (NT*8)-col tile over KSTEPS*8 k. Accumulates into acc.
template <int NT, int KSTEPS>
__device__ __forceinline__ void wmma_tile(const uint32_t* __restrict__ As,
                                          const uint32_t* __restrict__ Ws,
                                          float acc[2][NT][4], int tm, int lane) {
    int g = lane >> 2, tg = lane & 3;
    #pragma unroll
    for (int ks = 0; ks < KSTEPS; ks++) {
        int k0 = ks * 8;
        uint32_t a[2][4];
        #pragma unroll
        for (int mi = 0; mi < 2; mi++) {
            const uint32_t* ap = As + (tm + mi * 16 + g) * LDA + k0 + tg;
            a[mi][0] = ap[0];
            a[mi][1] = ap[8 * LDA];
            a[mi][2] = ap[4];
            a[mi][3] = ap[8 * LDA + 4];
        }
        #pragma unroll
        for (int ni = 0; ni < NT; ni++) {
            uint32_t b0 = Ws[(ni * 8 + g) * LDA + k0 + tg];
            uint32_t b1 = Ws[(ni * 8 + g) * LDA + k0 + tg + 4];
            mma8(acc[0][ni], a[0], b0, b1);
            mma8(acc[1][ni], a[1], b0, b1);
        }
    }
}

// ---------------------------------------------------------------------------
// K0: gather relative-position bias into [h][m][n]
// ---------------------------------------------------------------------------
__global__ void bias_kernel(const float* __restrict__ bias_table) {
    int m = blockIdx.x & 255;
    int h = blockIdx.x >> 8;
    int n = threadIdx.x;
    int dy = (n >> 4) - (m >> 4);
    int dx = (n & 15) - (m & 15);
    int idx = (dy + 15) * 31 + (dx + 15);
    g_bias[(h * NTOK + m) * NTOK + n] = bias_table[idx * NH + h];
}

// ---------------------------------------------------------------------------
// K1: window partition + LN1 + QKV GEMM (tf32 mma)
// ---------------------------------------------------------------------------
__global__ __launch_bounds__(256) void qkv_kernel(const float* __restrict__ x,
                                                  const float* __restrict__ qkv_w,
                                                  const float* __restrict__ qkv_b,
                                                  const float* __restrict__ ln_g,
                                                  const float* __restrict__ ln_b) {
    extern __shared__ uint32_t sm[];
    uint32_t* As = sm;               // [256][LDA]
    uint32_t* Ws = sm + NTOK * LDA;  // [96][LDA]
    int w = blockIdx.x, t = threadIdx.x;
    int lane = t & 31, wid = t >> 5, tm = wid * 32;
    int b = w >> 8, hb = (w >> 4) & 15, wb = w & 15;
    int d = t >> 6, ii = (t >> 3) & 7, jj = t & 7;
    const float* xp = x + ((size_t)b * CH * 4 + d) * 16384 + (hb * 8 + ii) * 128 + (wb * 8 + jj);

    float sum = 0.f, sq = 0.f;
    float* gt = g_t + ((size_t)w * NTOK + t) * CH;
    #pragma unroll 4
    for (int c = 0; c < CH; c++) {
        float v = xp[(size_t)c * 65536];
        sum += v; sq += v * v;
        As[t * LDA + c] = __float_as_uint(v);
        gt[c] = v;
    }
    float mean = sum * (1.f / CH);
    float rstd = rsqrtf(sq * (1.f / CH) - mean * mean + 1e-5f);
    #pragma unroll 4
    for (int c = 0; c < CH; c++) {
        float v = (__uint_as_float(As[t * LDA + c]) - mean) * rstd * __ldg(ln_g + c) + __ldg(ln_b + c);
        As[t * LDA + c] = f2tf(v);
    }

    for (int chunk = 0; chunk < 3; chunk++) {
        __syncthreads();  // (first iter: also makes As visible)
        for (int idx = t; idx < CH * CH; idx += 256) {
            int r = idx / CH, cc = idx - r * CH;
            Ws[r * LDA + cc] = f2tf(qkv_w[(chunk * CH + r) * CH + cc]);
        }
        __syncthreads();
        float acc[2][12][4];
        #pragma unroll
        for (int mi = 0; mi < 2; mi++)
            #pragma unroll
            for (int ni = 0; ni < 12; ni++)
                acc[mi][ni][0] = acc[mi][ni][1] = acc[mi][ni][2] = acc[mi][ni][3] = 0.f;
        wmma_tile<12, 12>(As, Ws, acc, tm, lane);

        float scale = (chunk == 0) ? 0.17677669529663687f : 1.f;
        int g = lane >> 2, tg = lane & 3;
        #pragma unroll
        for (int ni = 0; ni < 12; ni++) {
            int cn = ni * 8 + 2 * tg;
            int h = cn >> 5, dd = cn & 31;
            float b0v = qkv_b[chunk * CH + cn], b1v = qkv_b[chunk * CH + cn + 1];
            size_t base = (((size_t)w * 3 + chunk) * NH + h) * NTOK;
            #pragma unroll
            for (int mi = 0; mi < 2; mi++) {
                int r0 = tm + mi * 16 + g;
                float2 v0 = make_float2((acc[mi][ni][0] + b0v) * scale,
                                        (acc[mi][ni][1] + b1v) * scale);
                float2 v1 = make_float2((acc[mi][ni][2] + b0v) * scale,
                                        (acc[mi][ni][3] + b1v) * scale);
                *(float2*)&g_qkv[(base + r0) * HD + dd]     = v0;
                *(float2*)&g_qkv[(base + r0 + 8) * HD + dd] = v1;
            }
        }
    }
}

// ---------------------------------------------------------------------------
// K2: window attention (FFMA, online softmax), token-major qkv
// ---------------------------------------------------------------------------
__global__ __launch_bounds__(256) void attn_kernel() {
    extern __shared__ float smf[];
    float* k_s = smf;               // [m][36]
    float* v_s = smf + NTOK * 36;
    int bx = blockIdx.x;
    int w = bx / 3, h = bx % 3;
    int t = threadIdx.x;
    size_t qb = (((size_t)w * 3 + 0) * NH + h) * NTOK * HD;
    size_t kb = (((size_t)w * 3 + 1) * NH + h) * NTOK * HD;
    size_t vb = (((size_t)w * 3 + 2) * NH + h) * NTOK * HD;

    for (int idx = t; idx < NTOK * HD; idx += 256) {
        int m = idx >> 5, dd = idx & 31;
        k_s[m * 36 + dd] = g_qkv[kb + idx];
        v_s[m * 36 + dd] = g_qkv[vb + idx];
    }
    float qr[32];
    const float4* qp = (const float4*)&g_qkv[qb + (size_t)t * HD];
    #pragma unroll
    for (int dd = 0; dd < 8; dd++) {
        float4 qv = qp[dd];
        qr[4 * dd] = qv.x; qr[4 * dd + 1] = qv.y; qr[4 * dd + 2] = qv.z; qr[4 * dd + 3] = qv.w;
    }
    __syncthreads();

    const float* brow = g_bias + h * NTOK * NTOK + t;
    float maxv = -1e30f, ssum = 0.f;
    float acc[32];
    #pragma unroll
    for (int dd = 0; dd < 32; dd++) acc[dd] = 0.f;

    for (int m = 0; m < NTOK; m++) {
        float s = brow[m * NTOK];
        const float4* kr = (const float4*)&k_s[m * 36];
        #pragma unroll
        for (int dd = 0; dd < 8; dd++) {
            float4 kv = kr[dd];
            s += qr[4*dd] * kv.x + qr[4*dd+1] * kv.y + qr[4*dd+2] * kv.z + qr[4*dd+3] * kv.w;
        }
        const float4* vr = (const float4*)&v_s[m * 36];
        if (s <= maxv) {
            float p = __expf(s - maxv);
            ssum += p;
            #pragma unroll
            for (int dd = 0; dd < 8; dd++) {
                float4 vv = vr[dd];
                acc[4*dd]   += p * vv.x; acc[4*dd+1] += p * vv.y;
                acc[4*dd+2] += p * vv.z; acc[4*dd+3] += p * vv.w;
            }
        } else {
            float corr = __expf(maxv - s);
            ssum = ssum * corr + 1.f;
            #pragma unroll
            for (int dd = 0; dd < 8; dd++) {
                float4 vv = vr[dd];
                acc[4*dd]   = acc[4*dd]   * corr + vv.x;
                acc[4*dd+1] = acc[4*dd+1] * corr + vv.y;
                acc[4*dd+2] = acc[4*dd+2] * corr + vv.z;
                acc[4*dd+3] = acc[4*dd+3] * corr + vv.w;
            }
            maxv = s;
        }
    }
    float rinv = 1.f / ssum;
    float* op = g_o + ((size_t)w * NTOK + t) * CH + h * HD;
    #pragma unroll
    for (int dd = 0; dd < 8; dd++) {
        float4 r = make_float4(acc[4*dd] * rinv, acc[4*dd+1] * rinv,
                               acc[4*dd+2] * rinv, acc[4*dd+3] * rinv);
        *(float4*)&op[4 * dd] = r;
    }
}

// ---------------------------------------------------------------------------
// K3: proj + residual (tf32 mma), updates g_t in place
// ---------------------------------------------------------------------------
__global__ __launch_bounds__(256) void proj_kernel(const float* __restrict__ proj_w,
                                                   const float* __restrict__ proj_b) {
    extern __shared__ uint32_t sm[];
    uint32_t* As = sm;
    uint32_t* Ws = sm + NTOK * LDA;
    int w = blockIdx.x, t = threadIdx.x;
    int lane = t & 31, wid = t >> 5, tm = wid * 32;

    const float4* op = (const float4*)(g_o + ((size_t)w * NTOK + t) * CH);
    #pragma unroll
    for (int c4 = 0; c4 < 24; c4++) {
        float4 v = op[c4];
        uint4 u = make_uint4(f2tf(v.x), f2tf(v.y), f2tf(v.z), f2tf(v.w));
        *(uint4*)&As[t * LDA + 4 * c4] = u;
    }
    for (int idx = t; idx < CH * CH; idx += 256) {
        int r = idx / CH, cc = idx - r * CH;
        Ws[r * LDA + cc] = f2tf(proj_w[idx]);
    }
    __syncthreads();

    float acc[2][12][4];
    #pragma unroll
    for (int mi = 0; mi < 2; mi++)
        #pragma unroll
        for (int ni = 0; ni < 12; ni++)
            acc[mi][ni][0] = acc[mi][ni][1] = acc[mi][ni][2] = acc[mi][ni][3] = 0.f;
    wmma_tile<12, 12>(As, Ws, acc, tm, lane);

    int g = lane >> 2, tg = lane & 3;
    #pragma unroll
    for (int ni = 0; ni < 12; ni++) {
        int cn = ni * 8 + 2 * tg;
        float b0v = proj_b[cn], b1v = proj_b[cn + 1];
        #pragma unroll
        for (int mi = 0; mi < 2; mi++) {
            int r0 = tm + mi * 16 + g;
            float* t0 = &g_t[((size_t)w * NTOK + r0) * CH + cn];
            float* t1 = &g_t[((size_t)w * NTOK + r0 + 8) * CH + cn];
            float2 p0 = *(float2*)t0, p1 = *(float2*)t1;
            p0.x += acc[mi][ni][0] + b0v; p0.y += acc[mi][ni][1] + b1v;
            p1.x += acc[mi][ni][2] + b0v; p1.y += acc[mi][ni][3] + b1v;
            *(float2*)t0 = p0; *(float2*)t1 = p1;
        }
    }
}

// ---------------------------------------------------------------------------
// K4: LN2 + fc1 + exact GELU (tf32 mma) -> g_m (tf32 bits)
// ---------------------------------------------------------------------------
__global__ __launch_bounds__(256) void mlp1_kernel(const float* __restrict__ ln_g,
                                                   const float* __restrict__ ln_b,
                                                   const float* __restrict__ fc1_w,
                                                   const float* __restrict__ fc1_b) {
    extern __shared__ uint32_t sm[];
    uint32_t* As = sm;
    uint32_t* Ws = sm + NTOK * LDA;
    int w = blockIdx.x, t = threadIdx.x;
    int lane = t & 31, wid = t >> 5, tm = wid * 32;

    const float4* tp = (const float4*)(g_t + ((size_t)w * NTOK + t) * CH);
    float row[96];
    float sum = 0.f, sq = 0.f;
    #pragma unroll
    for (int c4 = 0; c4 < 24; c4++) {
        float4 v = tp[c4];
        row[4*c4] = v.x; row[4*c4+1] = v.y; row[4*c4+2] = v.z; row[4*c4+3] = v.w;
        sum += v.x + v.y + v.z + v.w;
        sq  += v.x*v.x + v.y*v.y + v.z*v.z + v.w*v.w;
    }
    float mean = sum * (1.f / CH);
    float rstd = rsqrtf(sq * (1.f / CH) - mean * mean + 1e-5f);
    #pragma unroll 4
    for (int c = 0; c < CH; c++)
        As[t * LDA + c] = f2tf((row[c] - mean) * rstd * __ldg(ln_g + c) + __ldg(ln_b + c));

    for (int chunk = 0; chunk < 4; chunk++) {
        __syncthreads();
        for (int idx = t; idx < CH * CH; idx += 256) {
            int r = idx / CH, cc = idx - r * CH;
            Ws[r * LDA + cc] = f2tf(fc1_w[(chunk * CH + r) * CH + cc]);
        }
        __syncthreads();
        float acc[2][12][4];
        #pragma unroll
        for (int mi = 0; mi < 2; mi++)
            #pragma unroll
            for (int ni = 0; ni < 12; ni++)
                acc[mi][ni][0] = acc[mi][ni][1] = acc[mi][ni][2] = acc[mi][ni][3] = 0.f;
        wmma_tile<12, 12>(As, Ws, acc, tm, lane);

        int g = lane >> 2, tg = lane & 3;
        #pragma unroll
        for (int ni = 0; ni < 12; ni++) {
            int cn = ni * 8 + 2 * tg;
            float b0v = fc1_b[chunk * CH + cn], b1v = fc1_b[chunk * CH + cn + 1];
            #pragma unroll
            for (int mi = 0; mi < 2; mi++) {
                int r0 = tm + mi * 16 + g;
                #pragma unroll
                for (int p = 0; p < 2; p++) {
                    int rr = r0 + p * 8;
                    float v0 = acc[mi][ni][2*p]   + b0v;
                    float v1 = acc[mi][ni][2*p+1] + b1v;
                    float g0 = 0.5f * v0 * (1.f + erff(v0 * 0.70710678118654752f));
                    float g1 = 0.5f * v1 * (1.f + erff(v1 * 0.70710678118654752f));
                    uint2 u = make_uint2(f2tf(g0), f2tf(g1));
                    *(uint2*)&g_m[((size_t)w * NTOK + rr) * HID + chunk * CH + cn] = u;
                }
            }
        }
    }
}

// ---------------------------------------------------------------------------
// K5: fc2 + residual -> out (tf32 mma)
// ---------------------------------------------------------------------------
__global__ __launch_bounds__(256) void mlp2_kernel(const float* __restrict__ fc2_w,
                                                   const float* __restrict__ fc2_b,
                                                   float* __restrict__ out) {
    extern __shared__ uint32_t sm[];
    uint32_t* As = sm;
    uint32_t* Ws = sm + NTOK * LDA;
    int w = blockIdx.x, t = threadIdx.x;
    int lane = t & 31, wid = t >> 5, tm = wid * 32;

    float acc[2][12][4];
    #pragma unroll
    for (int mi = 0; mi < 2; mi++)
        #pragma unroll
        for (int ni = 0; ni < 12; ni++)
            acc[mi][ni][0] = acc[mi][ni][1] = acc[mi][ni][2] = acc[mi][ni][3] = 0.f;

    for (int kt = 0; kt < 4; kt++) {
        __syncthreads();
        const uint4* mp = (const uint4*)(g_m + ((size_t)w * NTOK + t) * HID + kt * CH);
        #pragma unroll
        for (int c4 = 0; c4 < 24; c4++)
            *(uint4*)&As[t * LDA + 4 * c4] = mp[c4];
        for (int idx = t; idx < CH * CH; idx += 256) {
            int r = idx / CH, cc = idx - r * CH;
            Ws[r * LDA + cc] = f2tf(fc2_w[r * HID + kt * CH + cc]);
        }
        __syncthreads();
        wmma_tile<12, 12>(As, Ws, acc, tm, lane);
    }

    int g = lane >> 2, tg = lane & 3;
    #pragma unroll
    for (int ni = 0; ni < 12; ni++) {
        int cn = ni * 8 + 2 * tg;
        float b0v = fc2_b[cn], b1v = fc2_b[cn + 1];
        #pragma unroll
        for (int mi = 0; mi < 2; mi++) {
            int r0 = tm + mi * 16 + g;
            #pragma unroll
            for (int p = 0; p < 2; p++) {
                int rr = r0 + p * 8;
                const float2 tr = *(const float2*)&g_t[((size_t)w * NTOK + rr) * CH + cn];
                float2 v = make_float2(acc[mi][ni][2*p]   + b0v + tr.x,
                                       acc[mi][ni][2*p+1] + b1v + tr.y);
                *(float2*)&out[((size_t)w * NTOK + rr) * CH + cn] = v;
            }
        }
    }
}

// ---------------------------------------------------------------------------
extern "C" void kernel_launch(void* const* d_in, const int* in_sizes, int n_in,
                              void* d_out, int out_size) {
    (void)in_sizes; (void)n_in; (void)out_size;
    const float* x      = (const float*)d_in[0];
    const float* qkv_w  = (const float*)d_in[1];
    const float* qkv_b  = (const float*)d_in[2];
    const float* proj_w = (const float*)d_in[3];
    const float* proj_b = (const float*)d_in[4];
    const float* btab   = (const float*)d_in[5];
    const float* ln1_g  = (const float*)d_in[6];
    const float* ln1_b  = (const float*)d_in[7];
    const float* ln2_g  = (const float*)d_in[8];
    const float* ln2_b  = (const float*)d_in[9];
    const float* fc1_w  = (const float*)d_in[10];
    const float* fc1_b  = (const float*)d_in[11];
    const float* fc2_w  = (const float*)d_in[12];
    const float* fc2_b  = (const float*)d_in[13];
    float* out = (float*)d_out;

    const int smem_gemm = (NTOK * LDA + CH * LDA) * 4;  // 140800 B
    const int smem_attn = 2 * NTOK * 36 * 4;            //  73728 B
    cudaFuncSetAttribute(qkv_kernel,  cudaFuncAttributeMaxDynamicSharedMemorySize, smem_gemm);
    cudaFuncSetAttribute(attn_kernel, cudaFuncAttributeMaxDynamicSharedMemorySize, smem_attn);
    cudaFuncSetAttribute(proj_kernel, cudaFuncAttributeMaxDynamicSharedMemorySize, smem_gemm);
    cudaFuncSetAttribute(mlp1_kernel, cudaFuncAttributeMaxDynamicSharedMemorySize, smem_gemm);
    cudaFuncSetAttribute(mlp2_kernel, cudaFuncAttributeMaxDynamicSharedMemorySize, smem_gemm);

    bias_kernel<<<NH * NTOK, NTOK>>>(btab);
    qkv_kernel<<<NWIN, 256, smem_gemm>>>(x, qkv_w, qkv_b, ln1_g, ln1_b);
    attn_kernel<<<NWIN * NH, 256, smem_attn>>>();
    proj_kernel<<<NWIN, 256, smem_gemm>>>(proj_w, proj_b);
    mlp1_kernel<<<NWIN, 256, smem_gemm>>>(ln2_g, ln2_b, fc1_w, fc1_b);
    mlp2_kernel<<<NWIN, 256, smem_gemm>>>(fc2_w, fc2_b, out);
}

// round 3
// speedup vs baseline: 2.3169x; 1.4729x over previous
#include <cuda_runtime.h>
#include <math.h>
#include <stdint.h>

#define NWIN 512
#define NTOK 256
#define CH   96
#define NH   3
#define HD   32
#define HID  384
#define LDA  100   // smem row stride (words) -> conflict-free mma fragment loads

// Scratch (device globals)
__device__ float    g_t[(size_t)NWIN * NTOK * CH];            // residual, [w][t][c]
__device__ float    g_qkv[(size_t)NWIN * 3 * NH * NTOK * HD]; // [w][qkv][h][t][d]
__device__ float    g_o[(size_t)NWIN * NTOK * CH];            // attn out, [w][t][c]
__device__ uint32_t g_m[(size_t)NWIN * NTOK * HID];           // gelu(fc1) tf32 bits
__device__ float    g_bias[NH * NTOK * NTOK];                 // [h][m][n]

// ---------------------------------------------------------------------------
__device__ __forceinline__ uint32_t f2tf(float f) {
    uint32_t u;
    asm("cvt.rna.tf32.f32 %0, %1;" : "=r"(u) : "f"(f));
    return u;
}

__device__ __forceinline__ void mma8(float* c, const uint32_t* a, uint32_t b0, uint32_t b1) {
    asm("mma.sync.aligned.m16n8k8.row.col.f32.tf32.tf32.f32 "
        "{%0,%1,%2,%3},{%4,%5,%6,%7},{%8,%9},{%0,%1,%2,%3};"
        : "+f"(c[0]), "+f"(c[1]), "+f"(c[2]), "+f"(c[3])
        : "r"(a[0]), "r"(a[1]), "r"(a[2]), "r"(a[3]), "r"(b0), "r"(b1));
}

// Warp computes 16-row x (NT*8)-col tile over KSTEPS*8 k.
template <int NT, int KSTEPS>
__device__ __forceinline__ void wmma16(const uint32_t* __restrict__ As,
                                       const uint32_t* __restrict__ Ws,
                                       float acc[NT][4], int tm, int lane) {
    int g = lane >> 2, tg = lane & 3;
    #pragma unroll
    for (int ks = 0; ks < KSTEPS; ks++) {
        int k0 = ks * 8;
        const uint32_t* ap = As + (tm + g) * LDA + k0 + tg;
        uint32_t a[4] = {ap[0], ap[8 * LDA], ap[4], ap[8 * LDA + 4]};
        #pragma unroll
        for (int ni = 0; ni < NT; ni++) {
            uint32_t b0 = Ws[(ni * 8 + g) * LDA + k0 + tg];
            uint32_t b1 = Ws[(ni * 8 + g) * LDA + k0 + tg + 4];
            mma8(acc[ni], a, b0, b1);
        }
    }
}

// ---------------------------------------------------------------------------
// K0: gather relative-position bias into [h][m][n]
// ---------------------------------------------------------------------------
__global__ void bias_kernel(const float* __restrict__ bias_table) {
    int m = blockIdx.x & 255;
    int h = blockIdx.x >> 8;
    int n = threadIdx.x;
    int dy = (n >> 4) - (m >> 4);
    int dx = (n & 15) - (m & 15);
    int idx = (dy + 15) * 31 + (dx + 15);
    g_bias[(h * NTOK + m) * NTOK + n] = bias_table[idx * NH + h];
}

// ---------------------------------------------------------------------------
// K1: window partition + LN1 + QKV GEMM (tf32 mma), 128 tokens/CTA
// ---------------------------------------------------------------------------
__global__ __launch_bounds__(256) void qkv_kernel(const float* __restrict__ x,
                                                  const float* __restrict__ qkv_w,
                                                  const float* __restrict__ qkv_b,
                                                  const float* __restrict__ ln_g,
                                                  const float* __restrict__ ln_b) {
    extern __shared__ uint32_t sm[];
    uint32_t* As = sm;              // [128][LDA]
    uint32_t* Ws = sm + 128 * LDA;  // [96][LDA]
    int bw = blockIdx.x, w = bw >> 1, half = bw & 1;
    int t = threadIdx.x, lane = t & 31, wid = t >> 5, tm = wid * 16;
    int b = w >> 8, hb = (w >> 4) & 15, wb = w & 15;

    if (t < 128) {
        int tok = half * 128 + t;
        int d = tok >> 6, ii = (tok >> 3) & 7, jj = tok & 7;
        const float* xp = x + ((size_t)b * CH * 4 + d) * 16384 + (hb * 8 + ii) * 128 + (wb * 8 + jj);
        float row[96];
        float sum = 0.f, sq = 0.f;
        float* gt = g_t + ((size_t)w * NTOK + tok) * CH;
        #pragma unroll 4
        for (int c = 0; c < CH; c++) {
            float v = xp[(size_t)c * 65536];
            sum += v; sq += v * v;
            row[c] = v;
            gt[c] = v;
        }
        float mean = sum * (1.f / CH);
        float rstd = rsqrtf(sq * (1.f / CH) - mean * mean + 1e-5f);
        #pragma unroll 4
        for (int c = 0; c < CH; c++)
            As[t * LDA + c] = f2tf((row[c] - mean) * rstd * __ldg(ln_g + c) + __ldg(ln_b + c));
    }

    for (int chunk = 0; chunk < 3; chunk++) {
        __syncthreads();
        for (int idx = t; idx < CH * CH; idx += 256) {
            int r = idx / CH, cc = idx - r * CH;
            Ws[r * LDA + cc] = f2tf(qkv_w[(chunk * CH + r) * CH + cc]);
        }
        __syncthreads();
        float acc[12][4];
        #pragma unroll
        for (int ni = 0; ni < 12; ni++)
            acc[ni][0] = acc[ni][1] = acc[ni][2] = acc[ni][3] = 0.f;
        wmma16<12, 12>(As, Ws, acc, tm, lane);

        float scale = (chunk == 0) ? 0.17677669529663687f : 1.f;
        int g = lane >> 2, tg = lane & 3;
        #pragma unroll
        for (int ni = 0; ni < 12; ni++) {
            int cn = ni * 8 + 2 * tg;
            int h = cn >> 5, dd = cn & 31;
            float b0v = qkv_b[chunk * CH + cn], b1v = qkv_b[chunk * CH + cn + 1];
            size_t base = (((size_t)w * 3 + chunk) * NH + h) * NTOK;
            int r0 = half * 128 + tm + g;
            float2 v0 = make_float2((acc[ni][0] + b0v) * scale, (acc[ni][1] + b1v) * scale);
            float2 v1 = make_float2((acc[ni][2] + b0v) * scale, (acc[ni][3] + b1v) * scale);
            *(float2*)&g_qkv[(base + r0) * HD + dd]     = v0;
            *(float2*)&g_qkv[(base + r0 + 8) * HD + dd] = v1;
        }
    }
}

// ---------------------------------------------------------------------------
// K2: window attention, tf32 mma flash-style; one CTA per (window, head)
// ---------------------------------------------------------------------------
__global__ __launch_bounds__(256) void attn_kernel() {
    extern __shared__ uint32_t smu[];
    uint32_t* K_s  = smu;                       // [256][36]
    uint32_t* Vt_s = smu + NTOK * 36;           // [32][260]  (V transposed)
    uint32_t* P_s  = smu + NTOK * 36 + 32 * 260; // [256][68]
    int bx = blockIdx.x;
    int w = bx / 3, h = bx - w * 3;
    int t = threadIdx.x, lane = t & 31, wid = t >> 5;
    int g = lane >> 2, tg = lane & 3;
    int tm = wid * 32;
    size_t qb = (((size_t)w * 3 + 0) * NH + h) * NTOK * HD;
    size_t kb = (((size_t)w * 3 + 1) * NH + h) * NTOK * HD;
    size_t vb = (((size_t)w * 3 + 2) * NH + h) * NTOK * HD;

    for (int idx = t; idx < NTOK * HD; idx += 256) {
        int m = idx >> 5, d = idx & 31;
        K_s[m * 36 + d]  = f2tf(g_qkv[kb + idx]);
        Vt_s[d * 260 + m] = f2tf(g_qkv[vb + idx]);
    }
    // Q fragments in registers: qa[r4][s] = Q[tm + (r4>>1)*16 + (r4&1)*8 + g][tg + 4s]
    uint32_t qa[4][8];
    {
        const float* qp = g_qkv + qb;
        #pragma unroll
        for (int r4 = 0; r4 < 4; r4++) {
            int row = tm + (r4 >> 1) * 16 + (r4 & 1) * 8 + g;
            #pragma unroll
            for (int s8 = 0; s8 < 8; s8++)
                qa[r4][s8] = f2tf(qp[row * 32 + tg + 4 * s8]);
        }
    }
    __syncthreads();

    // per-lane rows: r=0: tm+g, r=1: tm+g+8, r=2: tm+16+g, r=3: tm+24+g
    float m_r[4], l_r[4];
    #pragma unroll
    for (int r = 0; r < 4; r++) { m_r[r] = -1e30f; l_r[r] = 0.f; }
    float o[2][4][4];
    #pragma unroll
    for (int mi = 0; mi < 2; mi++)
        #pragma unroll
        for (int ni = 0; ni < 4; ni++)
            o[mi][ni][0] = o[mi][ni][1] = o[mi][ni][2] = o[mi][ni][3] = 0.f;

    for (int j = 0; j < 4; j++) {
        // ---- S = Q @ K^T (32 rows x 64 cols) ----
        float s[2][8][4];
        #pragma unroll
        for (int mi = 0; mi < 2; mi++)
            #pragma unroll
            for (int ni = 0; ni < 8; ni++)
                s[mi][ni][0] = s[mi][ni][1] = s[mi][ni][2] = s[mi][ni][3] = 0.f;
        #pragma unroll
        for (int ks = 0; ks < 4; ks++) {
            uint32_t a0[4] = {qa[0][2*ks], qa[1][2*ks], qa[0][2*ks+1], qa[1][2*ks+1]};
            uint32_t a1[4] = {qa[2][2*ks], qa[3][2*ks], qa[2][2*ks+1], qa[3][2*ks+1]};
            #pragma unroll
            for (int ni = 0; ni < 8; ni++) {
                uint32_t b0 = K_s[(j * 64 + ni * 8 + g) * 36 + 8 * ks + tg];
                uint32_t b1 = K_s[(j * 64 + ni * 8 + g) * 36 + 8 * ks + tg + 4];
                mma8(s[0][ni], a0, b0, b1);
                mma8(s[1][ni], a1, b0, b1);
            }
        }
        // ---- bias + row max ----
        float mx[4] = {-1e30f, -1e30f, -1e30f, -1e30f};
        #pragma unroll
        for (int mi = 0; mi < 2; mi++)
            #pragma unroll
            for (int p = 0; p < 2; p++) {
                int r = mi * 2 + p;
                int row = tm + mi * 16 + p * 8 + g;
                const float* bp = g_bias + ((size_t)h * NTOK + row) * NTOK + j * 64 + 2 * tg;
                #pragma unroll
                for (int ni = 0; ni < 8; ni++) {
                    float2 bv = *(const float2*)(bp + ni * 8);
                    s[mi][ni][2*p]   += bv.x;
                    s[mi][ni][2*p+1] += bv.y;
                    mx[r] = fmaxf(mx[r], fmaxf(s[mi][ni][2*p], s[mi][ni][2*p+1]));
                }
            }
        float corr[4];
        #pragma unroll
        for (int r = 0; r < 4; r++) {
            mx[r] = fmaxf(mx[r], __shfl_xor_sync(0xffffffffu, mx[r], 1));
            mx[r] = fmaxf(mx[r], __shfl_xor_sync(0xffffffffu, mx[r], 2));
            float mnew = fmaxf(m_r[r], mx[r]);
            corr[r] = __expf(m_r[r] - mnew);
            m_r[r] = mnew;
            l_r[r] *= corr[r];
        }
        // rescale O
        #pragma unroll
        for (int mi = 0; mi < 2; mi++)
            #pragma unroll
            for (int p = 0; p < 2; p++) {
                float cc = corr[mi * 2 + p];
                #pragma unroll
                for (int ni = 0; ni < 4; ni++) {
                    o[mi][ni][2*p]   *= cc;
                    o[mi][ni][2*p+1] *= cc;
                }
            }
        // ---- exp + P store + row sum ----
        __syncwarp();
        float rsum[4] = {0.f, 0.f, 0.f, 0.f};
        #pragma unroll
        for (int mi = 0; mi < 2; mi++)
            #pragma unroll
            for (int p = 0; p < 2; p++) {
                int r = mi * 2 + p;
                int row = tm + mi * 16 + p * 8 + g;
                #pragma unroll
                for (int ni = 0; ni < 8; ni++) {
                    float p0 = __expf(s[mi][ni][2*p]   - m_r[r]);
                    float p1 = __expf(s[mi][ni][2*p+1] - m_r[r]);
                    rsum[r] += p0 + p1;
                    *(uint2*)&P_s[row * 68 + ni * 8 + 2 * tg] = make_uint2(f2tf(p0), f2tf(p1));
                }
            }
        #pragma unroll
        for (int r = 0; r < 4; r++) {
            rsum[r] += __shfl_xor_sync(0xffffffffu, rsum[r], 1);
            rsum[r] += __shfl_xor_sync(0xffffffffu, rsum[r], 2);
            l_r[r] += rsum[r];
        }
        __syncwarp();
        // ---- O += P @ V ----
        #pragma unroll
        for (int ks = 0; ks < 8; ks++) {
            int k0 = 8 * ks;
            uint32_t a[2][4];
            #pragma unroll
            for (int mi = 0; mi < 2; mi++) {
                const uint32_t* ap = P_s + (tm + mi * 16 + g) * 68 + k0 + tg;
                a[mi][0] = ap[0]; a[mi][1] = ap[8 * 68]; a[mi][2] = ap[4]; a[mi][3] = ap[8 * 68 + 4];
            }
            #pragma unroll
            for (int ni = 0; ni < 4; ni++) {
                uint32_t b0 = Vt_s[(ni * 8 + g) * 260 + j * 64 + k0 + tg];
                uint32_t b1 = Vt_s[(ni * 8 + g) * 260 + j * 64 + k0 + tg + 4];
                mma8(o[0][ni], a[0], b0, b1);
                mma8(o[1][ni], a[1], b0, b1);
            }
        }
    }
    // ---- normalize + write ----
    #pragma unroll
    for (int r = 0; r < 4; r++) l_r[r] = 1.f / l_r[r];
    #pragma unroll
    for (int mi = 0; mi < 2; mi++)
        #pragma unroll
        for (int p = 0; p < 2; p++) {
            int r = mi * 2 + p;
            int row = tm + mi * 16 + p * 8 + g;
            #pragma unroll
            for (int ni = 0; ni < 4; ni++) {
                float2 v = make_float2(o[mi][ni][2*p] * l_r[r], o[mi][ni][2*p+1] * l_r[r]);
                *(float2*)&g_o[((size_t)w * NTOK + row) * CH + h * HD + ni * 8 + 2 * tg] = v;
            }
        }
}

// ---------------------------------------------------------------------------
// K3: proj + residual (tf32 mma), 128 tokens/CTA
// ---------------------------------------------------------------------------
__global__ __launch_bounds__(256) void proj_kernel(const float* __restrict__ proj_w,
                                                   const float* __restrict__ proj_b) {
    extern __shared__ uint32_t sm[];
    uint32_t* As = sm;
    uint32_t* Ws = sm + 128 * LDA;
    int bw = blockIdx.x, w = bw >> 1, half = bw & 1;
    int t = threadIdx.x, lane = t & 31, wid = t >> 5, tm = wid * 16;

    for (int idx = t; idx < 128 * CH; idx += 256) {
        int r = idx / CH, cc = idx - r * CH;
        As[r * LDA + cc] = f2tf(g_o[((size_t)w * NTOK + half * 128 + r) * CH + cc]);
    }
    for (int idx = t; idx < CH * CH; idx += 256) {
        int r = idx / CH, cc = idx - r * CH;
        Ws[r * LDA + cc] = f2tf(proj_w[idx]);
    }
    __syncthreads();

    float acc[12][4];
    #pragma unroll
    for (int ni = 0; ni < 12; ni++)
        acc[ni][0] = acc[ni][1] = acc[ni][2] = acc[ni][3] = 0.f;
    wmma16<12, 12>(As, Ws, acc, tm, lane);

    int g = lane >> 2, tg = lane & 3;
    #pragma unroll
    for (int ni = 0; ni < 12; ni++) {
        int cn = ni * 8 + 2 * tg;
        float b0v = proj_b[cn], b1v = proj_b[cn + 1];
        int r0 = half * 128 + tm + g;
        float* t0 = &g_t[((size_t)w * NTOK + r0) * CH + cn];
        float* t1 = &g_t[((size_t)w * NTOK + r0 + 8) * CH + cn];
        float2 p0 = *(float2*)t0, p1 = *(float2*)t1;
        p0.x += acc[ni][0] + b0v; p0.y += acc[ni][1] + b1v;
        p1.x += acc[ni][2] + b0v; p1.y += acc[ni][3] + b1v;
        *(float2*)t0 = p0; *(float2*)t1 = p1;
    }
}

// ---------------------------------------------------------------------------
// K4: LN2 + fc1 + exact GELU (tf32 mma), 128 tokens/CTA
// ---------------------------------------------------------------------------
__global__ __launch_bounds__(256) void mlp1_kernel(const float* __restrict__ ln_g,
                                                   const float* __restrict__ ln_b,
                                                   const float* __restrict__ fc1_w,
                                                   const float* __restrict__ fc1_b) {
    extern __shared__ uint32_t sm[];
    uint32_t* As = sm;
    uint32_t* Ws = sm + 128 * LDA;
    int bw = blockIdx.x, w = bw >> 1, half = bw & 1;
    int t = threadIdx.x, lane = t & 31, wid = t >> 5, tm = wid * 16;

    if (t < 128) {
        int tok = half * 128 + t;
        const float4* tp = (const float4*)(g_t + ((size_t)w * NTOK + tok) * CH);
        float row[96];
        float sum = 0.f, sq = 0.f;
        #pragma unroll
        for (int c4 = 0; c4 < 24; c4++) {
            float4 v = tp[c4];
            row[4*c4] = v.x; row[4*c4+1] = v.y; row[4*c4+2] = v.z; row[4*c4+3] = v.w;
            sum += v.x + v.y + v.z + v.w;
            sq  += v.x*v.x + v.y*v.y + v.z*v.z + v.w*v.w;
        }
        float mean = sum * (1.f / CH);
        float rstd = rsqrtf(sq * (1.f / CH) - mean * mean + 1e-5f);
        #pragma unroll 4
        for (int c = 0; c < CH; c++)
            As[t * LDA + c] = f2tf((row[c] - mean) * rstd * __ldg(ln_g + c) + __ldg(ln_b + c));
    }

    for (int chunk = 0; chunk < 4; chunk++) {
        __syncthreads();
        for (int idx = t; idx < CH * CH; idx += 256) {
            int r = idx / CH, cc = idx - r * CH;
            Ws[r * LDA + cc] = f2tf(fc1_w[(chunk * CH + r) * CH + cc]);
        }
        __syncthreads();
        float acc[12][4];
        #pragma unroll
        for (int ni = 0; ni < 12; ni++)
            acc[ni][0] = acc[ni][1] = acc[ni][2] = acc[ni][3] = 0.f;
        wmma16<12, 12>(As, Ws, acc, tm, lane);

        int g = lane >> 2, tg = lane & 3;
        #pragma unroll
        for (int ni = 0; ni < 12; ni++) {
            int cn = ni * 8 + 2 * tg;
            float b0v = fc1_b[chunk * CH + cn], b1v = fc1_b[chunk * CH + cn + 1];
            #pragma unroll
            for (int p = 0; p < 2; p++) {
                int rr = half * 128 + tm + g + p * 8;
                float v0 = acc[ni][2*p]   + b0v;
                float v1 = acc[ni][2*p+1] + b1v;
                float g0 = 0.5f * v0 * (1.f + erff(v0 * 0.70710678118654752f));
                float g1 = 0.5f * v1 * (1.f + erff(v1 * 0.70710678118654752f));
                *(uint2*)&g_m[((size_t)w * NTOK + rr) * HID + chunk * CH + cn] =
                    make_uint2(f2tf(g0), f2tf(g1));
            }
        }
    }
}

// ---------------------------------------------------------------------------
// K5: fc2 + residual -> out (tf32 mma), 128 tokens/CTA
// ---------------------------------------------------------------------------
__global__ __launch_bounds__(256) void mlp2_kernel(const float* __restrict__ fc2_w,
                                                   const float* __restrict__ fc2_b,
                                                   float* __restrict__ out) {
    extern __shared__ uint32_t sm[];
    uint32_t* As = sm;
    uint32_t* Ws = sm + 128 * LDA;
    int bw = blockIdx.x, w = bw >> 1, half = bw & 1;
    int t = threadIdx.x, lane = t & 31, wid = t >> 5, tm = wid * 16;

    float acc[12][4];
    #pragma unroll
    for (int ni = 0; ni < 12; ni++)
        acc[ni][0] = acc[ni][1] = acc[ni][2] = acc[ni][3] = 0.f;

    for (int kt = 0; kt < 4; kt++) {
        __syncthreads();
        for (int idx = t; idx < 128 * CH; idx += 256) {
            int r = idx / CH, cc = idx - r * CH;
            As[r * LDA + cc] = g_m[((size_t)w * NTOK + half * 128 + r) * HID + kt * CH + cc];
        }
        for (int idx = t; idx < CH * CH; idx += 256) {
            int r = idx / CH, cc = idx - r * CH;
            Ws[r * LDA + cc] = f2tf(fc2_w[r * HID + kt * CH + cc]);
        }
        __syncthreads();
        wmma16<12, 12>(As, Ws, acc, tm, lane);
    }

    int g = lane >> 2, tg = lane & 3;
    #pragma unroll
    for (int ni = 0; ni < 12; ni++) {
        int cn = ni * 8 + 2 * tg;
        float b0v = fc2_b[cn], b1v = fc2_b[cn + 1];
        #pragma unroll
        for (int p = 0; p < 2; p++) {
            int rr = half * 128 + tm + g + p * 8;
            const float2 tr = *(const float2*)&g_t[((size_t)w * NTOK + rr) * CH + cn];
            float2 v = make_float2(acc[ni][2*p]   + b0v + tr.x,
                                   acc[ni][2*p+1] + b1v + tr.y);
            *(float2*)&out[((size_t)w * NTOK + rr) * CH + cn] = v;
        }
    }
}

// ---------------------------------------------------------------------------
extern "C" void kernel_launch(void* const* d_in, const int* in_sizes, int n_in,
                              void* d_out, int out_size) {
    (void)in_sizes; (void)n_in; (void)out_size;
    const float* x      = (const float*)d_in[0];
    const float* qkv_w  = (const float*)d_in[1];
    const float* qkv_b  = (const float*)d_in[2];
    const float* proj_w = (const float*)d_in[3];
    const float* proj_b = (const float*)d_in[4];
    const float* btab   = (const float*)d_in[5];
    const float* ln1_g  = (const float*)d_in[6];
    const float* ln1_b  = (const float*)d_in[7];
    const float* ln2_g  = (const float*)d_in[8];
    const float* ln2_b  = (const float*)d_in[9];
    const float* fc1_w  = (const float*)d_in[10];
    const float* fc1_b  = (const float*)d_in[11];
    const float* fc2_w  = (const float*)d_in[12];
    const float* fc2_b  = (const float*)d_in[13];
    float* out = (float*)d_out;

    const int smem_gemm = (128 * LDA + CH * LDA) * 4;              // 89600 B
    const int smem_attn = (NTOK * 36 + 32 * 260 + NTOK * 68) * 4;  // 139776 B
    cudaFuncSetAttribute(qkv_kernel,  cudaFuncAttributeMaxDynamicSharedMemorySize, smem_gemm);
    cudaFuncSetAttribute(attn_kernel, cudaFuncAttributeMaxDynamicSharedMemorySize, smem_attn);
    cudaFuncSetAttribute(proj_kernel, cudaFuncAttributeMaxDynamicSharedMemorySize, smem_gemm);
    cudaFuncSetAttribute(mlp1_kernel, cudaFuncAttributeMaxDynamicSharedMemorySize, smem_gemm);
    cudaFuncSetAttribute(mlp2_kernel, cudaFuncAttributeMaxDynamicSharedMemorySize, smem_gemm);

    bias_kernel<<<NH * NTOK, NTOK>>>(btab);
    qkv_kernel<<<NWIN * 2, 256, smem_gemm>>>(x, qkv_w, qkv_b, ln1_g, ln1_b);
    attn_kernel<<<NWIN * NH, 256, smem_attn>>>();
    proj_kernel<<<NWIN * 2, 256, smem_gemm>>>(proj_w, proj_b);
    mlp1_kernel<<<NWIN * 2, 256, smem_gemm>>>(ln2_g, ln2_b, fc1_w, fc1_b);
    mlp2_kernel<<<NWIN * 2, 256, smem_gemm>>>(fc2_w, fc2_b, out);
}

// round 4
// speedup vs baseline: 2.8861x; 1.2457x over previous
#include <cuda_runtime.h>
#include <math.h>
#include <stdint.h>

#define NWIN 512
#define NTOK 256
#define CH   96
#define NH   3
#define HD   32
#define HID  384
#define LDA  100   // smem row stride (words) -> conflict-free mma fragment loads

// Scratch (device globals)
__device__ float g_t[(size_t)NWIN * NTOK * CH];            // residual, [w][t][c]
__device__ float g_qkv[(size_t)NWIN * 3 * NH * NTOK * HD]; // [w][qkv][h][t][d]
__device__ float g_bias[NH * NTOK * NTOK];                 // [h][m][n]

// ---------------------------------------------------------------------------
__device__ __forceinline__ void cp_async16(void* s, const void* g) {
    uint32_t sa = (uint32_t)__cvta_generic_to_shared(s);
    asm volatile("cp.async.cg.shared.global [%0], [%1], 16;" :: "r"(sa), "l"(g));
}
#define CP_COMMIT asm volatile("cp.async.commit_group;")
#define CP_WAIT0  asm volatile("cp.async.wait_group 0;")

__device__ __forceinline__ void mma8(float* c, const uint32_t* a, uint32_t b0, uint32_t b1) {
    asm("mma.sync.aligned.m16n8k8.row.col.f32.tf32.tf32.f32 "
        "{%0,%1,%2,%3},{%4,%5,%6,%7},{%8,%9},{%0,%1,%2,%3};"
        : "+f"(c[0]), "+f"(c[1]), "+f"(c[2]), "+f"(c[3])
        : "r"(a[0]), "r"(a[1]), "r"(a[2]), "r"(a[3]), "r"(b0), "r"(b1));
}

// Warp computes 16-row x (NT*8)-col tile over KSTEPS*8 k (both operands stride LDA).
template <int NT, int KSTEPS>
__device__ __forceinline__ void wmma16(const uint32_t* __restrict__ As,
                                       const uint32_t* __restrict__ Ws,
                                       float acc[NT][4], int tm, int lane) {
    int g = lane >> 2, tg = lane & 3;
    #pragma unroll
    for (int ks = 0; ks < KSTEPS; ks++) {
        int k0 = ks * 8;
        const uint32_t* ap = As + (tm + g) * LDA + k0 + tg;
        uint32_t a[4] = {ap[0], ap[8 * LDA], ap[4], ap[8 * LDA + 4]};
        #pragma unroll
        for (int ni = 0; ni < NT; ni++) {
            uint32_t b0 = Ws[(ni * 8 + g) * LDA + k0 + tg];
            uint32_t b1 = Ws[(ni * 8 + g) * LDA + k0 + tg + 4];
            mma8(acc[ni], a, b0, b1);
        }
    }
}

// ---------------------------------------------------------------------------
// K0: gather relative-position bias into [h][m][n]
// ---------------------------------------------------------------------------
__global__ void bias_kernel(const float* __restrict__ bias_table) {
    int m = blockIdx.x & 255;
    int h = blockIdx.x >> 8;
    int n = threadIdx.x;
    int dy = (n >> 4) - (m >> 4);
    int dx = (n & 15) - (m & 15);
    int idx = (dy + 15) * 31 + (dx + 15);
    g_bias[(h * NTOK + m) * NTOK + n] = bias_table[idx * NH + h];
}

// ---------------------------------------------------------------------------
// K1: window partition + LN1 + QKV GEMM, 128 tokens/CTA, dbuf weights
// ---------------------------------------------------------------------------
__global__ __launch_bounds__(256) void qkv_kernel(const float* __restrict__ x,
                                                  const float* __restrict__ qkv_w,
                                                  const float* __restrict__ qkv_b,
                                                  const float* __restrict__ ln_g,
                                                  const float* __restrict__ ln_b) {
    extern __shared__ uint32_t sm[];
    uint32_t* As = sm;  // [128][LDA]
    uint32_t* Wb0 = sm + 128 * LDA;
    uint32_t* Wb1 = Wb0 + CH * LDA;
    int bw = blockIdx.x, w = bw >> 1, half = bw & 1;
    int t = threadIdx.x, lane = t & 31, wid = t >> 5, tm = wid * 16;
    int b = w >> 8, hb = (w >> 4) & 15, wb = w & 15;

    // prefetch weight chunk 0
    for (int idx = t; idx < CH * 24; idx += 256) {
        int r = idx / 24, c4 = idx - r * 24;
        cp_async16(&Wb0[r * LDA + c4 * 4], &qkv_w[r * CH + c4 * 4]);
    }
    CP_COMMIT;

    if (t < 128) {
        int tok = half * 128 + t;
        int d = tok >> 6, ii = (tok >> 3) & 7, jj = tok & 7;
        const float* xp = x + ((size_t)b * CH * 4 + d) * 16384 + (hb * 8 + ii) * 128 + (wb * 8 + jj);
        float row[96];
        float sum = 0.f, sq = 0.f;
        float* gt = g_t + ((size_t)w * NTOK + tok) * CH;
        #pragma unroll 4
        for (int c = 0; c < CH; c++) {
            float v = xp[(size_t)c * 65536];
            sum += v; sq += v * v;
            row[c] = v;
            gt[c] = v;
        }
        float mean = sum * (1.f / CH);
        float rstd = rsqrtf(sq * (1.f / CH) - mean * mean + 1e-5f);
        #pragma unroll 4
        for (int c = 0; c < CH; c++)
            As[t * LDA + c] = __float_as_uint((row[c] - mean) * rstd * __ldg(ln_g + c) + __ldg(ln_b + c));
    }

    for (int chunk = 0; chunk < 3; chunk++) {
        uint32_t* Wcur = (chunk & 1) ? Wb1 : Wb0;
        uint32_t* Wnxt = (chunk & 1) ? Wb0 : Wb1;
        CP_WAIT0;
        __syncthreads();
        if (chunk < 2) {
            for (int idx = t; idx < CH * 24; idx += 256) {
                int r = idx / 24, c4 = idx - r * 24;
                cp_async16(&Wnxt[r * LDA + c4 * 4], &qkv_w[((chunk + 1) * CH + r) * CH + c4 * 4]);
            }
            CP_COMMIT;
        }
        float acc[12][4];
        #pragma unroll
        for (int ni = 0; ni < 12; ni++)
            acc[ni][0] = acc[ni][1] = acc[ni][2] = acc[ni][3] = 0.f;
        wmma16<12, 12>(As, Wcur, acc, tm, lane);

        float scale = (chunk == 0) ? 0.17677669529663687f : 1.f;
        int g = lane >> 2, tg = lane & 3;
        #pragma unroll
        for (int ni = 0; ni < 12; ni++) {
            int cn = ni * 8 + 2 * tg;
            int h = cn >> 5, dd = cn & 31;
            float b0v = qkv_b[chunk * CH + cn], b1v = qkv_b[chunk * CH + cn + 1];
            size_t base = (((size_t)w * 3 + chunk) * NH + h) * NTOK;
            int r0 = half * 128 + tm + g;
            float2 v0 = make_float2((acc[ni][0] + b0v) * scale, (acc[ni][1] + b1v) * scale);
            float2 v1 = make_float2((acc[ni][2] + b0v) * scale, (acc[ni][3] + b1v) * scale);
            *(float2*)&g_qkv[(base + r0) * HD + dd]     = v0;
            *(float2*)&g_qkv[(base + r0 + 8) * HD + dd] = v1;
        }
    }
}

// ---------------------------------------------------------------------------
// K2: fused attention (3 heads) + proj + residual, one CTA per window
// smem: O_s[256][100] | P_s[256][68] | K_s[256][36] | Vt_s[32][68]; Ws overlays K_s
// ---------------------------------------------------------------------------
__global__ __launch_bounds__(256) void attn_kernel(const float* __restrict__ proj_w,
                                                   const float* __restrict__ proj_b) {
    extern __shared__ uint32_t smu[];
    uint32_t* O_s  = smu;                    // 25600 words
    uint32_t* P_s  = smu + 25600;            // 17408 words
    uint32_t* K_s  = smu + 43008;            // 9216 words
    uint32_t* Vt_s = smu + 52224;            // 2176 words
    uint32_t* Ws   = smu + 43008;            // overlay (proj phase), 9600 words
    int w = blockIdx.x;
    int t = threadIdx.x, lane = t & 31, wid = t >> 5;
    int g = lane >> 2, tg = lane & 3;
    int tm = wid * 32;

    for (int h = 0; h < NH; h++) {
        size_t qb = (((size_t)w * 3 + 0) * NH + h) * NTOK * HD;
        size_t kb = (((size_t)w * 3 + 1) * NH + h) * NTOK * HD;
        size_t vb = (((size_t)w * 3 + 2) * NH + h) * NTOK * HD;

        __syncthreads();  // K_s free (prev head's S mmas done)
        for (int idx = t; idx < NTOK * 8; idx += 256) {
            int m = idx >> 3, d4 = idx & 7;
            cp_async16(&K_s[m * 36 + d4 * 4], &g_qkv[kb + m * 32 + d4 * 4]);
        }
        CP_COMMIT;

        uint32_t qa[4][8];
        {
            const float* qp = g_qkv + qb;
            #pragma unroll
            for (int r4 = 0; r4 < 4; r4++) {
                int row = tm + (r4 >> 1) * 16 + (r4 & 1) * 8 + g;
                #pragma unroll
                for (int s8 = 0; s8 < 8; s8++)
                    qa[r4][s8] = __float_as_uint(qp[row * 32 + tg + 4 * s8]);
            }
        }
        CP_WAIT0;
        __syncthreads();

        float m_r[4], l_r[4];
        #pragma unroll
        for (int r = 0; r < 4; r++) { m_r[r] = -1e30f; l_r[r] = 0.f; }
        float o[2][4][4];
        #pragma unroll
        for (int mi = 0; mi < 2; mi++)
            #pragma unroll
            for (int ni = 0; ni < 4; ni++)
                o[mi][ni][0] = o[mi][ni][1] = o[mi][ni][2] = o[mi][ni][3] = 0.f;

        for (int j = 0; j < 4; j++) {
            __syncthreads();  // prev PV done; Vt_s free
            for (int idx = t; idx < 64 * 32; idx += 256) {
                int ml = idx >> 5, d = idx & 31;
                Vt_s[d * 68 + ml] = __float_as_uint(g_qkv[vb + (size_t)(j * 64 + ml) * 32 + d]);
            }
            __syncthreads();

            // ---- S = Q @ K^T (32 rows x 64 cols) ----
            float s[2][8][4];
            #pragma unroll
            for (int mi = 0; mi < 2; mi++)
                #pragma unroll
                for (int ni = 0; ni < 8; ni++)
                    s[mi][ni][0] = s[mi][ni][1] = s[mi][ni][2] = s[mi][ni][3] = 0.f;
            #pragma unroll
            for (int ks = 0; ks < 4; ks++) {
                uint32_t a0[4] = {qa[0][2*ks], qa[1][2*ks], qa[0][2*ks+1], qa[1][2*ks+1]};
                uint32_t a1[4] = {qa[2][2*ks], qa[3][2*ks], qa[2][2*ks+1], qa[3][2*ks+1]};
                #pragma unroll
                for (int ni = 0; ni < 8; ni++) {
                    uint32_t b0 = K_s[(j * 64 + ni * 8 + g) * 36 + 8 * ks + tg];
                    uint32_t b1 = K_s[(j * 64 + ni * 8 + g) * 36 + 8 * ks + tg + 4];
                    mma8(s[0][ni], a0, b0, b1);
                    mma8(s[1][ni], a1, b0, b1);
                }
            }
            // ---- bias + row max ----
            float mx[4] = {-1e30f, -1e30f, -1e30f, -1e30f};
            #pragma unroll
            for (int mi = 0; mi < 2; mi++)
                #pragma unroll
                for (int p = 0; p < 2; p++) {
                    int r = mi * 2 + p;
                    int row = tm + mi * 16 + p * 8 + g;
                    const float* bp = g_bias + ((size_t)h * NTOK + row) * NTOK + j * 64 + 2 * tg;
                    #pragma unroll
                    for (int ni = 0; ni < 8; ni++) {
                        float2 bv = *(const float2*)(bp + ni * 8);
                        s[mi][ni][2*p]   += bv.x;
                        s[mi][ni][2*p+1] += bv.y;
                        mx[r] = fmaxf(mx[r], fmaxf(s[mi][ni][2*p], s[mi][ni][2*p+1]));
                    }
                }
            float corr[4];
            #pragma unroll
            for (int r = 0; r < 4; r++) {
                mx[r] = fmaxf(mx[r], __shfl_xor_sync(0xffffffffu, mx[r], 1));
                mx[r] = fmaxf(mx[r], __shfl_xor_sync(0xffffffffu, mx[r], 2));
                float mnew = fmaxf(m_r[r], mx[r]);
                corr[r] = __expf(m_r[r] - mnew);
                m_r[r] = mnew;
                l_r[r] *= corr[r];
            }
            #pragma unroll
            for (int mi = 0; mi < 2; mi++)
                #pragma unroll
                for (int p = 0; p < 2; p++) {
                    float cc = corr[mi * 2 + p];
                    #pragma unroll
                    for (int ni = 0; ni < 4; ni++) {
                        o[mi][ni][2*p]   *= cc;
                        o[mi][ni][2*p+1] *= cc;
                    }
                }
            // ---- exp + P store + row sum ----
            __syncwarp();
            float rsum[4] = {0.f, 0.f, 0.f, 0.f};
            #pragma unroll
            for (int mi = 0; mi < 2; mi++)
                #pragma unroll
                for (int p = 0; p < 2; p++) {
                    int r = mi * 2 + p;
                    int row = tm + mi * 16 + p * 8 + g;
                    #pragma unroll
                    for (int ni = 0; ni < 8; ni++) {
                        float p0 = __expf(s[mi][ni][2*p]   - m_r[r]);
                        float p1 = __expf(s[mi][ni][2*p+1] - m_r[r]);
                        rsum[r] += p0 + p1;
                        *(uint2*)&P_s[row * 68 + ni * 8 + 2 * tg] =
                            make_uint2(__float_as_uint(p0), __float_as_uint(p1));
                    }
                }
            #pragma unroll
            for (int r = 0; r < 4; r++) {
                rsum[r] += __shfl_xor_sync(0xffffffffu, rsum[r], 1);
                rsum[r] += __shfl_xor_sync(0xffffffffu, rsum[r], 2);
                l_r[r] += rsum[r];
            }
            __syncwarp();
            // ---- O += P @ V ----
            #pragma unroll
            for (int ks = 0; ks < 8; ks++) {
                int k0 = 8 * ks;
                uint32_t a[2][4];
                #pragma unroll
                for (int mi = 0; mi < 2; mi++) {
                    const uint32_t* ap = P_s + (tm + mi * 16 + g) * 68 + k0 + tg;
                    a[mi][0] = ap[0]; a[mi][1] = ap[8 * 68]; a[mi][2] = ap[4]; a[mi][3] = ap[8 * 68 + 4];
                }
                #pragma unroll
                for (int ni = 0; ni < 4; ni++) {
                    uint32_t b0 = Vt_s[(ni * 8 + g) * 68 + k0 + tg];
                    uint32_t b1 = Vt_s[(ni * 8 + g) * 68 + k0 + tg + 4];
                    mma8(o[0][ni], a[0], b0, b1);
                    mma8(o[1][ni], a[1], b0, b1);
                }
            }
        }
        // ---- normalize, write O_s columns [h*32, h*32+32) ----
        #pragma unroll
        for (int r = 0; r < 4; r++) l_r[r] = 1.f / l_r[r];
        #pragma unroll
        for (int mi = 0; mi < 2; mi++)
            #pragma unroll
            for (int p = 0; p < 2; p++) {
                int r = mi * 2 + p;
                int row = tm + mi * 16 + p * 8 + g;
                #pragma unroll
                for (int ni = 0; ni < 4; ni++) {
                    *(uint2*)&O_s[row * LDA + h * 32 + ni * 8 + 2 * tg] =
                        make_uint2(__float_as_uint(o[mi][ni][2*p] * l_r[r]),
                                   __float_as_uint(o[mi][ni][2*p+1] * l_r[r]));
                }
            }
    }

    // ---- proj + residual ----
    __syncthreads();  // last head's K/V reads done; Ws overlay safe
    for (int idx = t; idx < CH * 24; idx += 256) {
        int r = idx / 24, c4 = idx - r * 24;
        cp_async16(&Ws[r * LDA + c4 * 4], &proj_w[r * CH + c4 * 4]);
    }
    CP_COMMIT;
    CP_WAIT0;
    __syncthreads();

    float accA[12][4], accB[12][4];
    #pragma unroll
    for (int ni = 0; ni < 12; ni++) {
        accA[ni][0] = accA[ni][1] = accA[ni][2] = accA[ni][3] = 0.f;
        accB[ni][0] = accB[ni][1] = accB[ni][2] = accB[ni][3] = 0.f;
    }
    wmma16<12, 12>(O_s, Ws, accA, tm, lane);
    wmma16<12, 12>(O_s, Ws, accB, tm + 16, lane);

    #pragma unroll
    for (int ni = 0; ni < 12; ni++) {
        int cn = ni * 8 + 2 * tg;
        float b0v = proj_b[cn], b1v = proj_b[cn + 1];
        #pragma unroll
        for (int p = 0; p < 2; p++) {
            int rowA = tm + p * 8 + g;
            int rowB = tm + 16 + p * 8 + g;
            float* tA = &g_t[((size_t)w * NTOK + rowA) * CH + cn];
            float* tB = &g_t[((size_t)w * NTOK + rowB) * CH + cn];
            float2 pA = *(float2*)tA, pB = *(float2*)tB;
            pA.x += accA[ni][2*p] + b0v;   pA.y += accA[ni][2*p+1] + b1v;
            pB.x += accB[ni][2*p] + b0v;   pB.y += accB[ni][2*p+1] + b1v;
            *(float2*)tA = pA; *(float2*)tB = pB;
        }
    }
}

// ---------------------------------------------------------------------------
// K3: fused MLP: LN2 + fc1 + GELU + fc2 + residual, 128 tokens/CTA, dbuf weights
// ---------------------------------------------------------------------------
__global__ __launch_bounds__(256) void mlp_kernel(const float* __restrict__ ln_g,
                                                  const float* __restrict__ ln_b,
                                                  const float* __restrict__ fc1_w,
                                                  const float* __restrict__ fc1_b,
                                                  const float* __restrict__ fc2_w,
                                                  const float* __restrict__ fc2_b,
                                                  float* __restrict__ out) {
    extern __shared__ uint32_t sm[];
    uint32_t* As = sm;              // [128][LDA]
    uint32_t* Hs = sm + 12800;      // [128][LDA]
    uint32_t* Wb0 = sm + 25600;     // [96][LDA]
    uint32_t* Wb1 = sm + 35200;     // [96][LDA]
    int bw = blockIdx.x, w = bw >> 1, half = bw & 1;
    int t = threadIdx.x, lane = t & 31, wid = t >> 5, tm = wid * 16;
    int g = lane >> 2, tg = lane & 3;

    // prefetch fc1 chunk 0 into Wb0
    for (int idx = t; idx < CH * 24; idx += 256) {
        int r = idx / 24, c4 = idx - r * 24;
        cp_async16(&Wb0[r * LDA + c4 * 4], &fc1_w[r * CH + c4 * 4]);
    }
    CP_COMMIT;

    if (t < 128) {
        int tok = half * 128 + t;
        const float4* tp = (const float4*)(g_t + ((size_t)w * NTOK + tok) * CH);
        float row[96];
        float sum = 0.f, sq = 0.f;
        #pragma unroll
        for (int c4 = 0; c4 < 24; c4++) {
            float4 v = tp[c4];
            row[4*c4] = v.x; row[4*c4+1] = v.y; row[4*c4+2] = v.z; row[4*c4+3] = v.w;
            sum += v.x + v.y + v.z + v.w;
            sq  += v.x*v.x + v.y*v.y + v.z*v.z + v.w*v.w;
        }
        float mean = sum * (1.f / CH);
        float rstd = rsqrtf(sq * (1.f / CH) - mean * mean + 1e-5f);
        #pragma unroll 4
        for (int c = 0; c < CH; c++)
            As[t * LDA + c] = __float_as_uint((row[c] - mean) * rstd * __ldg(ln_g + c) + __ldg(ln_b + c));
    }

    float acc2[12][4];
    #pragma unroll
    for (int ni = 0; ni < 12; ni++)
        acc2[ni][0] = acc2[ni][1] = acc2[ni][2] = acc2[ni][3] = 0.f;

    for (int c = 0; c < 4; c++) {
        CP_WAIT0;
        __syncthreads();          // Wb0 = fc1 chunk c ready; prev fc2 mma done
        // prefetch fc2 chunk c into Wb1 (overlaps fc1 mma)
        for (int idx = t; idx < CH * 24; idx += 256) {
            int r = idx / 24, c4 = idx - r * 24;
            cp_async16(&Wb1[r * LDA + c4 * 4], &fc2_w[r * HID + c * CH + c4 * 4]);
        }
        CP_COMMIT;

        float acc1[12][4];
        #pragma unroll
        for (int ni = 0; ni < 12; ni++)
            acc1[ni][0] = acc1[ni][1] = acc1[ni][2] = acc1[ni][3] = 0.f;
        wmma16<12, 12>(As, Wb0, acc1, tm, lane);

        // gelu -> Hs (per-warp rows)
        #pragma unroll
        for (int ni = 0; ni < 12; ni++) {
            int cn = ni * 8 + 2 * tg;
            float b0v = fc1_b[c * CH + cn], b1v = fc1_b[c * CH + cn + 1];
            #pragma unroll
            for (int p = 0; p < 2; p++) {
                int row = tm + p * 8 + g;
                float v0 = acc1[ni][2*p]   + b0v;
                float v1 = acc1[ni][2*p+1] + b1v;
                float g0 = 0.5f * v0 * (1.f + erff(v0 * 0.70710678118654752f));
                float g1 = 0.5f * v1 * (1.f + erff(v1 * 0.70710678118654752f));
                *(uint2*)&Hs[row * LDA + cn] =
                    make_uint2(__float_as_uint(g0), __float_as_uint(g1));
            }
        }
        CP_WAIT0;
        __syncthreads();          // Wb1 = fc2 chunk c ready; Hs visible
        // prefetch next fc1 chunk into Wb0 (overlaps fc2 mma)
        if (c < 3) {
            for (int idx = t; idx < CH * 24; idx += 256) {
                int r = idx / 24, c4 = idx - r * 24;
                cp_async16(&Wb0[r * LDA + c4 * 4], &fc1_w[((c + 1) * CH + r) * CH + c4 * 4]);
            }
            CP_COMMIT;
        }
        wmma16<12, 12>(Hs, Wb1, acc2, tm, lane);
    }

    // epilogue: + bias + residual -> out
    #pragma unroll
    for (int ni = 0; ni < 12; ni++) {
        int cn = ni * 8 + 2 * tg;
        float b0v = fc2_b[cn], b1v = fc2_b[cn + 1];
        #pragma unroll
        for (int p = 0; p < 2; p++) {
            int row = half * 128 + tm + p * 8 + g;
            const float2 tr = *(const float2*)&g_t[((size_t)w * NTOK + row) * CH + cn];
            float2 v = make_float2(acc2[ni][2*p]   + b0v + tr.x,
                                   acc2[ni][2*p+1] + b1v + tr.y);
            *(float2*)&out[((size_t)w * NTOK + row) * CH + cn] = v;
        }
    }
}

// ---------------------------------------------------------------------------
extern "C" void kernel_launch(void* const* d_in, const int* in_sizes, int n_in,
                              void* d_out, int out_size) {
    (void)in_sizes; (void)n_in; (void)out_size;
    const float* x      = (const float*)d_in[0];
    const float* qkv_w  = (const float*)d_in[1];
    const float* qkv_b  = (const float*)d_in[2];
    const float* proj_w = (const float*)d_in[3];
    const float* proj_b = (const float*)d_in[4];
    const float* btab   = (const float*)d_in[5];
    const float* ln1_g  = (const float*)d_in[6];
    const float* ln1_b  = (const float*)d_in[7];
    const float* ln2_g  = (const float*)d_in[8];
    const float* ln2_b  = (const float*)d_in[9];
    const float* fc1_w  = (const float*)d_in[10];
    const float* fc1_b  = (const float*)d_in[11];
    const float* fc2_w  = (const float*)d_in[12];
    const float* fc2_b  = (const float*)d_in[13];
    float* out = (float*)d_out;

    const int smem_qkv  = (128 * LDA + 2 * CH * LDA) * 4;           // 128000 B
    const int smem_attn = (25600 + 17408 + 9216 + 2176) * 4;        // 217600 B
    const int smem_mlp  = (2 * 128 * LDA + 2 * CH * LDA) * 4;       // 179200 B
    cudaFuncSetAttribute(qkv_kernel,  cudaFuncAttributeMaxDynamicSharedMemorySize, smem_qkv);
    cudaFuncSetAttribute(attn_kernel, cudaFuncAttributeMaxDynamicSharedMemorySize, smem_attn);
    cudaFuncSetAttribute(mlp_kernel,  cudaFuncAttributeMaxDynamicSharedMemorySize, smem_mlp);

    bias_kernel<<<NH * NTOK, NTOK>>>(btab);
    qkv_kernel<<<NWIN * 2, 256, smem_qkv>>>(x, qkv_w, qkv_b, ln1_g, ln1_b);
    attn_kernel<<<NWIN, 256, smem_attn>>>(proj_w, proj_b);
    mlp_kernel<<<NWIN * 2, 256, smem_mlp>>>(ln2_g, ln2_b, fc1_w, fc1_b, fc2_w, fc2_b, out);
}

// round 5
// speedup vs baseline: 4.1120x; 1.4247x over previous
#include <cuda_runtime.h>
#include <cuda_bf16.h>
#include <math.h>
#include <stdint.h>

#define NWIN 512
#define NTOK 256
#define CH   96
#define NH   3
#define HD   32
#define HID  384
#define LDW  52    // pair-stride (uint32 units) for 96-wide bf16 operands

// Scratch (device globals)
__device__ float         g_t[(size_t)NWIN * NTOK * CH];       // residual, fp32 [w][t][c]
__device__ __nv_bfloat16 g_q[(size_t)NWIN * NH * NTOK * HD];  // [w][h][t][d]
__device__ __nv_bfloat16 g_k[(size_t)NWIN * NH * NTOK * HD];
__device__ float         g_v[(size_t)NWIN * NH * NTOK * HD];  // fp32 (transposed at use)
__device__ float         g_bias[NH * NTOK * NTOK];            // [h][m][n]
// weights pre-converted to bf16x2 pairs, row-major [rows][K/2]
__device__ uint32_t gw_qkv[288 * 48];
__device__ uint32_t gw_proj[96 * 48];
__device__ uint32_t gw_fc1[384 * 48];
__device__ uint32_t gw_fc2[96 * 192];

// ---------------------------------------------------------------------------
__device__ __forceinline__ void cp_async16(void* s, const void* g) {
    uint32_t sa = (uint32_t)__cvta_generic_to_shared(s);
    asm volatile("cp.async.cg.shared.global [%0], [%1], 16;" :: "r"(sa), "l"(g));
}
#define CP_COMMIT asm volatile("cp.async.commit_group;")
#define CP_WAIT0  asm volatile("cp.async.wait_group 0;")

__device__ __forceinline__ uint32_t pk(float a, float b) {
    __nv_bfloat162 h = __floats2bfloat162_rn(a, b);
    return *(uint32_t*)&h;
}

__device__ __forceinline__ void bmma(float* c, const uint32_t* a, uint32_t b0, uint32_t b1) {
    asm("mma.sync.aligned.m16n8k16.row.col.f32.bf16.bf16.f32 "
        "{%0,%1,%2,%3},{%4,%5,%6,%7},{%8,%9},{%0,%1,%2,%3};"
        : "+f"(c[0]), "+f"(c[1]), "+f"(c[2]), "+f"(c[3])
        : "r"(a[0]), "r"(a[1]), "r"(a[2]), "r"(a[3]), "r"(b0), "r"(b1));
}

// Warp computes 16-row x (NT*8)-col tile over KS*16 k. A rows at tm..tm+15.
template <int NT, int KS>
__device__ __forceinline__ void bgemm16(const uint32_t* __restrict__ As,
                                        const uint32_t* __restrict__ Ws,
                                        float acc[NT][4], int tm, int lane) {
    int g = lane >> 2, tg = lane & 3;
    #pragma unroll
    for (int ks = 0; ks < KS; ks++) {
        int k0 = ks * 8;
        const uint32_t* ap = As + (tm + g) * LDW + k0 + tg;
        uint32_t a[4] = {ap[0], ap[8 * LDW], ap[4], ap[8 * LDW + 4]};
        #pragma unroll
        for (int ni = 0; ni < NT; ni++) {
            uint32_t b0 = Ws[(ni * 8 + g) * LDW + k0 + tg];
            uint32_t b1 = Ws[(ni * 8 + g) * LDW + k0 + tg + 4];
            bmma(acc[ni], a, b0, b1);
        }
    }
}

// ---------------------------------------------------------------------------
// K0a: pre-convert all weights to bf16x2 pair layout
// ---------------------------------------------------------------------------
__global__ void prep_kernel(const float* __restrict__ qkv_w, const float* __restrict__ proj_w,
                            const float* __restrict__ fc1_w, const float* __restrict__ fc2_w) {
    int i = blockIdx.x * 256 + threadIdx.x;
    if (i < 13824) {
        int r = i / 48, p = i % 48;
        gw_qkv[i] = pk(qkv_w[r * 96 + 2 * p], qkv_w[r * 96 + 2 * p + 1]);
        return;
    }
    i -= 13824;
    if (i < 4608) {
        int r = i / 48, p = i % 48;
        gw_proj[i] = pk(proj_w[r * 96 + 2 * p], proj_w[r * 96 + 2 * p + 1]);
        return;
    }
    i -= 4608;
    if (i < 18432) {
        int r = i / 48, p = i % 48;
        gw_fc1[i] = pk(fc1_w[r * 96 + 2 * p], fc1_w[r * 96 + 2 * p + 1]);
        return;
    }
    i -= 18432;
    if (i < 18432) {
        int r = i / 192, p = i % 192;
        gw_fc2[i] = pk(fc2_w[r * 384 + 2 * p], fc2_w[r * 384 + 2 * p + 1]);
    }
}

// ---------------------------------------------------------------------------
// K0b: gather relative-position bias into [h][m][n]
// ---------------------------------------------------------------------------
__global__ void bias_kernel(const float* __restrict__ bias_table) {
    int m = blockIdx.x & 255;
    int h = blockIdx.x >> 8;
    int n = threadIdx.x;
    int dy = (n >> 4) - (m >> 4);
    int dx = (n & 15) - (m & 15);
    int idx = (dy + 15) * 31 + (dx + 15);
    g_bias[(h * NTOK + m) * NTOK + n] = bias_table[idx * NH + h];
}

// ---------------------------------------------------------------------------
// K1: window partition + LN1 + QKV GEMM (bf16 mma), 128 tokens/CTA
// ---------------------------------------------------------------------------
__global__ __launch_bounds__(256) void qkv_kernel(const float* __restrict__ x,
                                                  const float* __restrict__ qkv_b,
                                                  const float* __restrict__ ln_g,
                                                  const float* __restrict__ ln_b) {
    extern __shared__ uint32_t sm[];
    uint32_t* As  = sm;               // [128][LDW]
    uint32_t* Wb0 = sm + 128 * LDW;   // [96][LDW]
    uint32_t* Wb1 = Wb0 + 96 * LDW;
    int bw = blockIdx.x, w = bw >> 1, half = bw & 1;
    int t = threadIdx.x, lane = t & 31, wid = t >> 5, tm = wid * 16;
    int g = lane >> 2, tg = lane & 3;
    int b = w >> 8, hb = (w >> 4) & 15, wb = w & 15;

    for (int idx = t; idx < 96 * 12; idx += 256) {
        int r = idx / 12, c4 = idx % 12;
        cp_async16(&Wb0[r * LDW + c4 * 4], &gw_qkv[r * 48 + c4 * 4]);
    }
    CP_COMMIT;

    if (t < 128) {
        int tok = half * 128 + t;
        int d = tok >> 6, ii = (tok >> 3) & 7, jj = tok & 7;
        const float* xp = x + ((size_t)b * CH * 4 + d) * 16384 + (hb * 8 + ii) * 128 + (wb * 8 + jj);
        float row[96];
        float sum = 0.f, sq = 0.f;
        float* gt = g_t + ((size_t)w * NTOK + tok) * CH;
        #pragma unroll 4
        for (int c = 0; c < CH; c++) {
            float v = xp[(size_t)c * 65536];
            sum += v; sq += v * v;
            row[c] = v;
            gt[c] = v;
        }
        float mean = sum * (1.f / CH);
        float rstd = rsqrtf(sq * (1.f / CH) - mean * mean + 1e-5f);
        #pragma unroll
        for (int p = 0; p < 48; p++) {
            float n0 = (row[2*p]   - mean) * rstd * __ldg(ln_g + 2*p)   + __ldg(ln_b + 2*p);
            float n1 = (row[2*p+1] - mean) * rstd * __ldg(ln_g + 2*p+1) + __ldg(ln_b + 2*p+1);
            As[t * LDW + p] = pk(n0, n1);
        }
    }

    for (int chunk = 0; chunk < 3; chunk++) {
        uint32_t* Wc = (chunk & 1) ? Wb1 : Wb0;
        uint32_t* Wn = (chunk & 1) ? Wb0 : Wb1;
        CP_WAIT0;
        __syncthreads();
        if (chunk < 2) {
            for (int idx = t; idx < 96 * 12; idx += 256) {
                int r = idx / 12, c4 = idx % 12;
                cp_async16(&Wn[r * LDW + c4 * 4], &gw_qkv[((chunk + 1) * 96 + r) * 48 + c4 * 4]);
            }
            CP_COMMIT;
        }
        float acc[12][4];
        #pragma unroll
        for (int ni = 0; ni < 12; ni++)
            acc[ni][0] = acc[ni][1] = acc[ni][2] = acc[ni][3] = 0.f;
        bgemm16<12, 6>(As, Wc, acc, tm, lane);

        float scale = (chunk == 0) ? 0.17677669529663687f : 1.f;
        #pragma unroll
        for (int ni = 0; ni < 12; ni++) {
            int cn = ni * 8 + 2 * tg;
            int h = cn >> 5, dd = cn & 31;
            float b0v = qkv_b[chunk * CH + cn], b1v = qkv_b[chunk * CH + cn + 1];
            size_t base = ((size_t)(w * NH + h)) * NTOK;
            #pragma unroll
            for (int p = 0; p < 2; p++) {
                int row = half * 128 + tm + p * 8 + g;
                float v0 = acc[ni][2*p]   + b0v;
                float v1 = acc[ni][2*p+1] + b1v;
                if (chunk == 0) {
                    *(uint32_t*)&g_q[(base + row) * HD + dd] = pk(v0 * scale, v1 * scale);
                } else if (chunk == 1) {
                    *(uint32_t*)&g_k[(base + row) * HD + dd] = pk(v0, v1);
                } else {
                    *(float2*)&g_v[(base + row) * HD + dd] = make_float2(v0, v1);
                }
            }
        }
    }
}

// ---------------------------------------------------------------------------
// K2: fused attention (3 heads) + proj + residual; one CTA per 128 q-tokens
// smem words: O_s[128][52]=6656 | P_s[128][36]=4608 | K_s[256][28]=7168 | Vt_s[32][36]=1152
// Ws (proj weights) overlays K_s.
// ---------------------------------------------------------------------------
__global__ __launch_bounds__(256) void attn_kernel(const float* __restrict__ proj_b) {
    extern __shared__ uint32_t smu[];
    uint32_t* O_s  = smu;            // 6656
    uint32_t* P_s  = smu + 6656;     // 4608
    uint32_t* K_s  = smu + 11264;    // 7168
    uint32_t* Vt_s = smu + 18432;    // 1152
    uint32_t* Ws   = smu + 11264;    // overlay
    int bw = blockIdx.x, w = bw >> 1, half = bw & 1;
    int t = threadIdx.x, lane = t & 31, wid = t >> 5, tm = wid * 16;
    int g = lane >> 2, tg = lane & 3;

    for (int h = 0; h < NH; h++) {
        size_t hb = ((size_t)(w * NH + h)) * NTOK * HD;

        __syncthreads();  // prior head's K_s reads complete
        for (int idx = t; idx < 1024; idx += 256) {
            int m = idx >> 2, c = idx & 3;
            cp_async16(&K_s[m * 28 + c * 4], &g_k[hb + m * 32 + c * 8]);
        }
        CP_COMMIT;

        uint32_t qa[2][4];
        {
            int qrow = half * 128 + tm + g;
            #pragma unroll
            for (int ks = 0; ks < 2; ks++) {
                qa[ks][0] = *(const uint32_t*)&g_q[hb + (size_t)qrow * 32 + 16 * ks + 2 * tg];
                qa[ks][1] = *(const uint32_t*)&g_q[hb + (size_t)(qrow + 8) * 32 + 16 * ks + 2 * tg];
                qa[ks][2] = *(const uint32_t*)&g_q[hb + (size_t)qrow * 32 + 16 * ks + 2 * tg + 8];
                qa[ks][3] = *(const uint32_t*)&g_q[hb + (size_t)(qrow + 8) * 32 + 16 * ks + 2 * tg + 8];
            }
        }
        CP_WAIT0;
        __syncthreads();

        float m_r[2] = {-1e30f, -1e30f}, l_r[2] = {0.f, 0.f};
        float o[4][4];
        #pragma unroll
        for (int ni = 0; ni < 4; ni++)
            o[ni][0] = o[ni][1] = o[ni][2] = o[ni][3] = 0.f;

        for (int j = 0; j < 4; j++) {
            __syncthreads();  // prev PV reads of Vt_s complete
            for (int idx = t; idx < 1024; idx += 256) {
                int mp = idx >> 5, d = idx & 31;
                float v0 = g_v[hb + (size_t)(j * 64 + 2 * mp) * 32 + d];
                float v1 = g_v[hb + (size_t)(j * 64 + 2 * mp + 1) * 32 + d];
                Vt_s[d * 36 + mp] = pk(v0, v1);
            }
            __syncthreads();

            // ---- S = Q @ K^T (16 rows x 64 cols) ----
            float s[8][4];
            #pragma unroll
            for (int ni = 0; ni < 8; ni++)
                s[ni][0] = s[ni][1] = s[ni][2] = s[ni][3] = 0.f;
            #pragma unroll
            for (int ks = 0; ks < 2; ks++)
                #pragma unroll
                for (int ni = 0; ni < 8; ni++) {
                    uint32_t b0 = K_s[(j * 64 + ni * 8 + g) * 28 + 8 * ks + tg];
                    uint32_t b1 = K_s[(j * 64 + ni * 8 + g) * 28 + 8 * ks + tg + 4];
                    bmma(s[ni], qa[ks], b0, b1);
                }
            // ---- bias + row max ----
            float mx[2] = {-1e30f, -1e30f};
            #pragma unroll
            for (int p = 0; p < 2; p++) {
                int row = half * 128 + tm + p * 8 + g;
                const float* bp = g_bias + ((size_t)h * NTOK + row) * NTOK + j * 64 + 2 * tg;
                #pragma unroll
                for (int ni = 0; ni < 8; ni++) {
                    float2 bv = *(const float2*)(bp + ni * 8);
                    s[ni][2*p]   += bv.x;
                    s[ni][2*p+1] += bv.y;
                    mx[p] = fmaxf(mx[p], fmaxf(s[ni][2*p], s[ni][2*p+1]));
                }
            }
            float corr[2];
            #pragma unroll
            for (int p = 0; p < 2; p++) {
                mx[p] = fmaxf(mx[p], __shfl_xor_sync(0xffffffffu, mx[p], 1));
                mx[p] = fmaxf(mx[p], __shfl_xor_sync(0xffffffffu, mx[p], 2));
                float mnew = fmaxf(m_r[p], mx[p]);
                corr[p] = __expf(m_r[p] - mnew);
                m_r[p] = mnew;
                l_r[p] *= corr[p];
            }
            #pragma unroll
            for (int ni = 0; ni < 4; ni++) {
                o[ni][0] *= corr[0]; o[ni][1] *= corr[0];
                o[ni][2] *= corr[1]; o[ni][3] *= corr[1];
            }
            // ---- exp + P store + row sum ----
            float rsum[2] = {0.f, 0.f};
            #pragma unroll
            for (int p = 0; p < 2; p++) {
                int rloc = tm + p * 8 + g;
                #pragma unroll
                for (int ni = 0; ni < 8; ni++) {
                    float p0 = __expf(s[ni][2*p]   - m_r[p]);
                    float p1 = __expf(s[ni][2*p+1] - m_r[p]);
                    rsum[p] += p0 + p1;
                    P_s[rloc * 36 + ni * 4 + tg] = pk(p0, p1);
                }
            }
            #pragma unroll
            for (int p = 0; p < 2; p++) {
                rsum[p] += __shfl_xor_sync(0xffffffffu, rsum[p], 1);
                rsum[p] += __shfl_xor_sync(0xffffffffu, rsum[p], 2);
                l_r[p] += rsum[p];
            }
            __syncwarp();
            // ---- O += P @ V ----
            #pragma unroll
            for (int ks = 0; ks < 4; ks++) {
                int k0 = 8 * ks;
                const uint32_t* ap = P_s + (tm + g) * 36 + k0 + tg;
                uint32_t a[4] = {ap[0], ap[8 * 36], ap[4], ap[8 * 36 + 4]};
                #pragma unroll
                for (int ni = 0; ni < 4; ni++) {
                    uint32_t b0 = Vt_s[(ni * 8 + g) * 36 + k0 + tg];
                    uint32_t b1 = Vt_s[(ni * 8 + g) * 36 + k0 + tg + 4];
                    bmma(o[ni], a, b0, b1);
                }
            }
            __syncwarp();
        }
        // ---- normalize, write O_s pair-cols [h*16, h*16+16) ----
        float rinv[2] = {1.f / l_r[0], 1.f / l_r[1]};
        #pragma unroll
        for (int p = 0; p < 2; p++) {
            int rloc = tm + p * 8 + g;
            #pragma unroll
            for (int ni = 0; ni < 4; ni++)
                O_s[rloc * LDW + h * 16 + ni * 4 + tg] =
                    pk(o[ni][2*p] * rinv[p], o[ni][2*p+1] * rinv[p]);
        }
    }

    // ---- proj + residual ----
    __syncthreads();
    for (int idx = t; idx < 96 * 12; idx += 256) {
        int r = idx / 12, c4 = idx % 12;
        cp_async16(&Ws[r * LDW + c4 * 4], &gw_proj[r * 48 + c4 * 4]);
    }
    CP_COMMIT;
    CP_WAIT0;
    __syncthreads();

    float acc[12][4];
    #pragma unroll
    for (int ni = 0; ni < 12; ni++)
        acc[ni][0] = acc[ni][1] = acc[ni][2] = acc[ni][3] = 0.f;
    bgemm16<12, 6>(O_s, Ws, acc, tm, lane);

    #pragma unroll
    for (int ni = 0; ni < 12; ni++) {
        int cn = ni * 8 + 2 * tg;
        float b0v = proj_b[cn], b1v = proj_b[cn + 1];
        #pragma unroll
        for (int p = 0; p < 2; p++) {
            int row = half * 128 + tm + p * 8 + g;
            float* tp = &g_t[((size_t)w * NTOK + row) * CH + cn];
            float2 pr = *(float2*)tp;
            pr.x += acc[ni][2*p]   + b0v;
            pr.y += acc[ni][2*p+1] + b1v;
            *(float2*)tp = pr;
        }
    }
}

// ---------------------------------------------------------------------------
// K3: fused MLP: LN2 + fc1 + GELU + fc2 + residual, 128 tokens/CTA
// ---------------------------------------------------------------------------
__global__ __launch_bounds__(256) void mlp_kernel(const float* __restrict__ ln_g,
                                                  const float* __restrict__ ln_b,
                                                  const float* __restrict__ fc1_b,
                                                  const float* __restrict__ fc2_b,
                                                  float* __restrict__ out) {
    extern __shared__ uint32_t sm[];
    uint32_t* As  = sm;              // [128][LDW]
    uint32_t* Hs  = sm + 6656;       // [128][LDW]
    uint32_t* Wb0 = sm + 13312;      // [96][LDW]
    uint32_t* Wb1 = sm + 18304;      // [96][LDW]
    int bw = blockIdx.x, w = bw >> 1, half = bw & 1;
    int t = threadIdx.x, lane = t & 31, wid = t >> 5, tm = wid * 16;
    int g = lane >> 2, tg = lane & 3;

    for (int idx = t; idx < 96 * 12; idx += 256) {
        int r = idx / 12, c4 = idx % 12;
        cp_async16(&Wb0[r * LDW + c4 * 4], &gw_fc1[r * 48 + c4 * 4]);
    }
    CP_COMMIT;

    if (t < 128) {
        int tok = half * 128 + t;
        const float4* tp = (const float4*)(g_t + ((size_t)w * NTOK + tok) * CH);
        float row[96];
        float sum = 0.f, sq = 0.f;
        #pragma unroll
        for (int c4 = 0; c4 < 24; c4++) {
            float4 v = tp[c4];
            row[4*c4] = v.x; row[4*c4+1] = v.y; row[4*c4+2] = v.z; row[4*c4+3] = v.w;
            sum += v.x + v.y + v.z + v.w;
            sq  += v.x*v.x + v.y*v.y + v.z*v.z + v.w*v.w;
        }
        float mean = sum * (1.f / CH);
        float rstd = rsqrtf(sq * (1.f / CH) - mean * mean + 1e-5f);
        #pragma unroll
        for (int p = 0; p < 48; p++) {
            float n0 = (row[2*p]   - mean) * rstd * __ldg(ln_g + 2*p)   + __ldg(ln_b + 2*p);
            float n1 = (row[2*p+1] - mean) * rstd * __ldg(ln_g + 2*p+1) + __ldg(ln_b + 2*p+1);
            As[t * LDW + p] = pk(n0, n1);
        }
    }

    float acc2[12][4];
    #pragma unroll
    for (int ni = 0; ni < 12; ni++)
        acc2[ni][0] = acc2[ni][1] = acc2[ni][2] = acc2[ni][3] = 0.f;

    for (int c = 0; c < 4; c++) {
        CP_WAIT0;
        __syncthreads();          // Wb0 = fc1 chunk c ready; prev fc2 mma done
        for (int idx = t; idx < 96 * 12; idx += 256) {
            int r = idx / 12, c4 = idx % 12;
            cp_async16(&Wb1[r * LDW + c4 * 4], &gw_fc2[r * 192 + c * 48 + c4 * 4]);
        }
        CP_COMMIT;

        float acc1[12][4];
        #pragma unroll
        for (int ni = 0; ni < 12; ni++)
            acc1[ni][0] = acc1[ni][1] = acc1[ni][2] = acc1[ni][3] = 0.f;
        bgemm16<12, 6>(As, Wb0, acc1, tm, lane);

        #pragma unroll
        for (int ni = 0; ni < 12; ni++) {
            int cn = ni * 8 + 2 * tg;
            float b0v = fc1_b[c * CH + cn], b1v = fc1_b[c * CH + cn + 1];
            #pragma unroll
            for (int p = 0; p < 2; p++) {
                int rloc = tm + p * 8 + g;
                float v0 = acc1[ni][2*p]   + b0v;
                float v1 = acc1[ni][2*p+1] + b1v;
                float g0 = 0.5f * v0 * (1.f + erff(v0 * 0.70710678118654752f));
                float g1 = 0.5f * v1 * (1.f + erff(v1 * 0.70710678118654752f));
                Hs[rloc * LDW + ni * 4 + tg] = pk(g0, g1);
            }
        }
        CP_WAIT0;
        __syncthreads();          // Wb1 = fc2 chunk c ready; Hs visible
        if (c < 3) {
            for (int idx = t; idx < 96 * 12; idx += 256) {
                int r = idx / 12, c4 = idx % 12;
                cp_async16(&Wb0[r * LDW + c4 * 4], &gw_fc1[((c + 1) * 96 + r) * 48 + c4 * 4]);
            }
            CP_COMMIT;
        }
        bgemm16<12, 6>(Hs, Wb1, acc2, tm, lane);
    }

    #pragma unroll
    for (int ni = 0; ni < 12; ni++) {
        int cn = ni * 8 + 2 * tg;
        float b0v = fc2_b[cn], b1v = fc2_b[cn + 1];
        #pragma unroll
        for (int p = 0; p < 2; p++) {
            int row = half * 128 + tm + p * 8 + g;
            const float2 tr = *(const float2*)&g_t[((size_t)w * NTOK + row) * CH + cn];
            float2 v = make_float2(acc2[ni][2*p]   + b0v + tr.x,
                                   acc2[ni][2*p+1] + b1v + tr.y);
            *(float2*)&out[((size_t)w * NTOK + row) * CH + cn] = v;
        }
    }
}

// ---------------------------------------------------------------------------
extern "C" void kernel_launch(void* const* d_in, const int* in_sizes, int n_in,
                              void* d_out, int out_size) {
    (void)in_sizes; (void)n_in; (void)out_size;
    const float* x      = (const float*)d_in[0];
    const float* qkv_w  = (const float*)d_in[1];
    const float* qkv_b  = (const float*)d_in[2];
    const float* proj_w = (const float*)d_in[3];
    const float* proj_b = (const float*)d_in[4];
    const float* btab   = (const float*)d_in[5];
    const float* ln1_g  = (const float*)d_in[6];
    const float* ln1_b  = (const float*)d_in[7];
    const float* ln2_g  = (const float*)d_in[8];
    const float* ln2_b  = (const float*)d_in[9];
    const float* fc1_w  = (const float*)d_in[10];
    const float* fc1_b  = (const float*)d_in[11];
    const float* fc2_w  = (const float*)d_in[12];
    const float* fc2_b  = (const float*)d_in[13];
    float* out = (float*)d_out;

    const int smem_qkv  = (128 * LDW + 2 * 96 * LDW) * 4;            // 66560 B
    const int smem_attn = (6656 + 4608 + 7168 + 1152) * 4;           // 78336 B
    const int smem_mlp  = (2 * 128 * LDW + 2 * 96 * LDW) * 4;        // 93184 B
    cudaFuncSetAttribute(qkv_kernel,  cudaFuncAttributeMaxDynamicSharedMemorySize, smem_qkv);
    cudaFuncSetAttribute(attn_kernel, cudaFuncAttributeMaxDynamicSharedMemorySize, smem_attn);
    cudaFuncSetAttribute(mlp_kernel,  cudaFuncAttributeMaxDynamicSharedMemorySize, smem_mlp);

    prep_kernel<<<216, 256>>>(qkv_w, proj_w, fc1_w, fc2_w);
    bias_kernel<<<NH * NTOK, NTOK>>>(btab);
    qkv_kernel<<<NWIN * 2, 256, smem_qkv>>>(x, qkv_b, ln1_g, ln1_b);
    attn_kernel<<<NWIN * 2, 256, smem_attn>>>(proj_b);
    mlp_kernel<<<NWIN * 2, 256, smem_mlp>>>(ln2_g, ln2_b, fc1_b, fc2_b, out);
}

// round 6
// speedup vs baseline: 5.0476x; 1.2275x over previous
#include <cuda_runtime.h>
#include <cuda_bf16.h>
#include <math.h>
#include <stdint.h>

#define NWIN 512
#define NTOK 256
#define CH   96
#define NH   3
#define HD   32
#define HID  384
#define LDW  56    // stride (uint32) for 96-wide (48-pair) operand rows
#define LDK  40    // stride for 16/32-pair rows (K_s, P_s, Vt_s)

// storage position of logical pair p (within-8 permute so (tg,tg+4) are adjacent)
__device__ __forceinline__ int PERM(int p) {
    return (p & ~7) | ((p & 3) << 1) | ((p >> 2) & 1);
}

// Scratch (device globals)
__device__ float         g_t[(size_t)NWIN * NTOK * CH];       // residual fp32 [w][t][c]
__device__ __nv_bfloat16 g_q[(size_t)NWIN * NH * NTOK * HD];  // pair-permuted
__device__ __nv_bfloat16 g_k[(size_t)NWIN * NH * NTOK * HD];  // pair-permuted
__device__ float         g_v[(size_t)NWIN * NH * NTOK * HD];  // fp32 [m][d]
__device__ float         g_bias[NH * NTOK * NTOK];            // [h][m][n]
// weights as bf16x2 pairs, pair-permuted rows
__device__ uint32_t gw_qkv[288 * 48];
__device__ uint32_t gw_proj[96 * 48];
__device__ uint32_t gw_fc1[384 * 48];
__device__ uint32_t gw_fc2[96 * 192];

// ---------------------------------------------------------------------------
__device__ __forceinline__ void cp_async16(void* s, const void* g) {
    uint32_t sa = (uint32_t)__cvta_generic_to_shared(s);
    asm volatile("cp.async.cg.shared.global [%0], [%1], 16;" :: "r"(sa), "l"(g));
}
#define CP_COMMIT asm volatile("cp.async.commit_group;")
#define CP_WAIT0  asm volatile("cp.async.wait_group 0;")

__device__ __forceinline__ uint32_t pk(float a, float b) {
    __nv_bfloat162 h = __floats2bfloat162_rn(a, b);
    return *(uint32_t*)&h;
}

__device__ __forceinline__ void bmma(float* c, const uint32_t* a, uint32_t b0, uint32_t b1) {
    asm("mma.sync.aligned.m16n8k16.row.col.f32.bf16.bf16.f32 "
        "{%0,%1,%2,%3},{%4,%5,%6,%7},{%8,%9},{%0,%1,%2,%3};"
        : "+f"(c[0]), "+f"(c[1]), "+f"(c[2]), "+f"(c[3])
        : "r"(a[0]), "r"(a[1]), "r"(a[2]), "r"(a[3]), "r"(b0), "r"(b1));
}

// 16 rows x NT*8 cols over KS*16 k; permuted layouts, LDS.64 operand loads.
template <int NT, int KS, int SA, int SB>
__device__ __forceinline__ void bgemm16(const uint32_t* __restrict__ As,
                                        const uint32_t* __restrict__ Ws,
                                        float acc[NT][4], int tm, int lane) {
    int g = lane >> 2, tg = lane & 3;
    #pragma unroll
    for (int ks = 0; ks < KS; ks++) {
        int o = 8 * ks + 2 * tg;
        uint2 x = *(const uint2*)(As + (tm + g) * SA + o);
        uint2 y = *(const uint2*)(As + (tm + 8 + g) * SA + o);
        uint32_t a[4] = {x.x, y.x, x.y, y.y};
        #pragma unroll
        for (int ni = 0; ni < NT; ni++) {
            uint2 b = *(const uint2*)(Ws + (ni * 8 + g) * SB + o);
            bmma(acc[ni], a, b.x, b.y);
        }
    }
}

// ---------------------------------------------------------------------------
// K0a: weights -> bf16x2 pair-permuted
// ---------------------------------------------------------------------------
__global__ void prep_kernel(const float* __restrict__ qkv_w, const float* __restrict__ proj_w,
                            const float* __restrict__ fc1_w, const float* __restrict__ fc2_w) {
    int i = blockIdx.x * 256 + threadIdx.x;
    if (i < 13824) {
        int r = i / 48, p = i % 48;
        gw_qkv[r * 48 + PERM(p)] = pk(qkv_w[r * 96 + 2 * p], qkv_w[r * 96 + 2 * p + 1]);
        return;
    }
    i -= 13824;
    if (i < 4608) {
        int r = i / 48, p = i % 48;
        gw_proj[r * 48 + PERM(p)] = pk(proj_w[r * 96 + 2 * p], proj_w[r * 96 + 2 * p + 1]);
        return;
    }
    i -= 4608;
    if (i < 18432) {
        int r = i / 48, p = i % 48;
        gw_fc1[r * 48 + PERM(p)] = pk(fc1_w[r * 96 + 2 * p], fc1_w[r * 96 + 2 * p + 1]);
        return;
    }
    i -= 18432;
    if (i < 18432) {
        int r = i / 192, p = i % 192;
        gw_fc2[r * 192 + PERM(p)] = pk(fc2_w[r * 384 + 2 * p], fc2_w[r * 384 + 2 * p + 1]);
    }
}

// ---------------------------------------------------------------------------
// K0b: gather relative-position bias into [h][m][n]
// ---------------------------------------------------------------------------
__global__ void bias_kernel(const float* __restrict__ bias_table) {
    int m = blockIdx.x & 255;
    int h = blockIdx.x >> 8;
    int n = threadIdx.x;
    int dy = (n >> 4) - (m >> 4);
    int dx = (n & 15) - (m & 15);
    int idx = (dy + 15) * 31 + (dx + 15);
    g_bias[(h * NTOK + m) * NTOK + n] = bias_table[idx * NH + h];
}

// ---------------------------------------------------------------------------
// K1: window partition + LN1 + QKV GEMM, 128 tokens/CTA
// ---------------------------------------------------------------------------
__global__ __launch_bounds__(256, 2) void qkv_kernel(const float* __restrict__ x,
                                                     const float* __restrict__ qkv_b,
                                                     const float* __restrict__ ln_g,
                                                     const float* __restrict__ ln_b) {
    extern __shared__ uint32_t sm[];
    uint32_t* As  = sm;               // [128][LDW]
    uint32_t* Wb0 = sm + 128 * LDW;
    uint32_t* Wb1 = Wb0 + 96 * LDW;
    int bw = blockIdx.x, w = bw >> 1, half = bw & 1;
    int t = threadIdx.x, lane = t & 31, wid = t >> 5, tm = wid * 16;
    int g = lane >> 2, tg = lane & 3;
    int b = w >> 8, hb = (w >> 4) & 15, wb = w & 15;

    for (int idx = t; idx < 96 * 12; idx += 256) {
        int r = idx / 12, c4 = idx % 12;
        cp_async16(&Wb0[r * LDW + c4 * 4], &gw_qkv[r * 48 + c4 * 4]);
    }
    CP_COMMIT;

    if (t < 128) {
        int tok = half * 128 + t;
        int d = tok >> 6, ii = (tok >> 3) & 7, jj = tok & 7;
        const float* xp = x + ((size_t)b * CH * 4 + d) * 16384 + (hb * 8 + ii) * 128 + (wb * 8 + jj);
        float row[96];
        float sum = 0.f, sq = 0.f;
        float* gt = g_t + ((size_t)w * NTOK + tok) * CH;
        #pragma unroll 4
        for (int c = 0; c < CH; c++) {
            float v = xp[(size_t)c * 65536];
            sum += v; sq += v * v;
            row[c] = v;
            gt[c] = v;
        }
        float mean = sum * (1.f / CH);
        float rstd = rsqrtf(sq * (1.f / CH) - mean * mean + 1e-5f);
        #pragma unroll
        for (int p = 0; p < 48; p++) {
            float n0 = (row[2*p]   - mean) * rstd * __ldg(ln_g + 2*p)   + __ldg(ln_b + 2*p);
            float n1 = (row[2*p+1] - mean) * rstd * __ldg(ln_g + 2*p+1) + __ldg(ln_b + 2*p+1);
            As[t * LDW + PERM(p)] = pk(n0, n1);
        }
    }

    for (int chunk = 0; chunk < 3; chunk++) {
        uint32_t* Wc = (chunk & 1) ? Wb1 : Wb0;
        uint32_t* Wn = (chunk & 1) ? Wb0 : Wb1;
        CP_WAIT0;
        __syncthreads();
        if (chunk < 2) {
            for (int idx = t; idx < 96 * 12; idx += 256) {
                int r = idx / 12, c4 = idx % 12;
                cp_async16(&Wn[r * LDW + c4 * 4], &gw_qkv[((chunk + 1) * 96 + r) * 48 + c4 * 4]);
            }
            CP_COMMIT;
        }
        float acc[12][4];
        #pragma unroll
        for (int ni = 0; ni < 12; ni++)
            acc[ni][0] = acc[ni][1] = acc[ni][2] = acc[ni][3] = 0.f;
        bgemm16<12, 6, LDW, LDW>(As, Wc, acc, tm, lane);

        float scale = (chunk == 0) ? 0.17677669529663687f : 1.f;
        #pragma unroll
        for (int ni = 0; ni < 12; ni++) {
            int cn = ni * 8 + 2 * tg;
            int h = cn >> 5, dd = cn & 31;
            float b0v = qkv_b[chunk * CH + cn], b1v = qkv_b[chunk * CH + cn + 1];
            size_t base = ((size_t)(w * NH + h)) * NTOK;
            #pragma unroll
            for (int p = 0; p < 2; p++) {
                int row = half * 128 + tm + p * 8 + g;
                float v0 = acc[ni][2*p]   + b0v;
                float v1 = acc[ni][2*p+1] + b1v;
                if (chunk == 0) {
                    *(uint32_t*)&g_q[(base + row) * HD + 2 * PERM(dd >> 1)] = pk(v0 * scale, v1 * scale);
                } else if (chunk == 1) {
                    *(uint32_t*)&g_k[(base + row) * HD + 2 * PERM(dd >> 1)] = pk(v0, v1);
                } else {
                    *(float2*)&g_v[(base + row) * HD + dd] = make_float2(v0, v1);
                }
            }
        }
    }
}

// ---------------------------------------------------------------------------
// K2: fused attention (3 heads) + proj + residual; one CTA per 128 q-tokens
// smem words: O_s[128][56] | P_s[128][40] | K_s[256][40] | Vt_s[2][32][40]
// ---------------------------------------------------------------------------
__global__ __launch_bounds__(256, 2) void attn_kernel(const float* __restrict__ proj_b) {
    extern __shared__ uint32_t smu[];
    uint32_t* O_s = smu;               // 7168
    uint32_t* P_s = smu + 7168;        // 5120
    uint32_t* K_s = smu + 12288;       // 10240
    uint32_t* Vt0 = smu + 22528;       // 1280
    uint32_t* Vt1 = smu + 23808;       // 1280
    uint32_t* Ws  = smu + 12288;       // overlay (proj)
    int bw = blockIdx.x, w = bw >> 1, half = bw & 1;
    int t = threadIdx.x, lane = t & 31, wid = t >> 5, tm = wid * 16;
    int g = lane >> 2, tg = lane & 3;
    int vmp = t >> 5 << 2, vd = 0;  // placeholder (recomputed below)

    for (int h = 0; h < NH; h++) {
        size_t hb = ((size_t)(w * NH + h)) * NTOK * HD;

        __syncthreads();  // prior head's K_s / Vt reads complete
        for (int idx = t; idx < 1024; idx += 256) {
            int m = idx >> 2, c = idx & 3;
            cp_async16(&K_s[m * LDK + c * 4], &g_k[hb + m * 32 + c * 8]);
        }
        CP_COMMIT;

        // Q fragments (permuted gmem pairs -> adjacent uint2)
        uint32_t qa[2][4];
        {
            int qrow = half * 128 + tm + g;
            #pragma unroll
            for (int ks = 0; ks < 2; ks++) {
                uint2 ua = *(const uint2*)&g_q[hb + (size_t)qrow * 32 + 16 * ks + 4 * tg];
                uint2 ub = *(const uint2*)&g_q[hb + (size_t)(qrow + 8) * 32 + 16 * ks + 4 * tg];
                qa[ks][0] = ua.x; qa[ks][1] = ub.x; qa[ks][2] = ua.y; qa[ks][3] = ub.y;
            }
        }
        // stage Vt tile 0
        {
            float2 vr[4];
            #pragma unroll
            for (int ii = 0; ii < 4; ii++) {
                int idx = ii * 256 + t;
                int mp = idx >> 5, d = idx & 31;
                vr[ii].x = g_v[hb + (size_t)(2 * mp) * 32 + d];
                vr[ii].y = g_v[hb + (size_t)(2 * mp + 1) * 32 + d];
            }
            #pragma unroll
            for (int ii = 0; ii < 4; ii++) {
                int idx = ii * 256 + t;
                int mp = idx >> 5, d = idx & 31;
                Vt0[d * LDK + PERM(mp)] = pk(vr[ii].x, vr[ii].y);
            }
        }
        CP_WAIT0;
        __syncthreads();

        float m_r[2] = {-1e30f, -1e30f}, l_r[2] = {0.f, 0.f};
        float o[4][4];
        #pragma unroll
        for (int ni = 0; ni < 4; ni++)
            o[ni][0] = o[ni][1] = o[ni][2] = o[ni][3] = 0.f;

        for (int j = 0; j < 4; j++) {
            uint32_t* Vcur = (j & 1) ? Vt1 : Vt0;
            uint32_t* Vnxt = (j & 1) ? Vt0 : Vt1;
            // issue next V-tile loads (latency hidden under S+softmax)
            float2 vr[4];
            if (j < 3) {
                #pragma unroll
                for (int ii = 0; ii < 4; ii++) {
                    int idx = ii * 256 + t;
                    int mp = idx >> 5, d = idx & 31;
                    vr[ii].x = g_v[hb + (size_t)((j + 1) * 64 + 2 * mp) * 32 + d];
                    vr[ii].y = g_v[hb + (size_t)((j + 1) * 64 + 2 * mp + 1) * 32 + d];
                }
            }
            // ---- S = Q K^T (16 x 64) ----
            float s[8][4];
            #pragma unroll
            for (int ni = 0; ni < 8; ni++)
                s[ni][0] = s[ni][1] = s[ni][2] = s[ni][3] = 0.f;
            #pragma unroll
            for (int ks = 0; ks < 2; ks++) {
                int off = 8 * ks + 2 * tg;
                #pragma unroll
                for (int ni = 0; ni < 8; ni++) {
                    uint2 bq = *(const uint2*)(K_s + (j * 64 + ni * 8 + g) * LDK + off);
                    bmma(s[ni], qa[ks], bq.x, bq.y);
                }
            }
            // ---- bias + row max ----
            float mx[2] = {-1e30f, -1e30f};
            #pragma unroll
            for (int p = 0; p < 2; p++) {
                int row = half * 128 + tm + p * 8 + g;
                const float* bp = g_bias + ((size_t)h * NTOK + row) * NTOK + j * 64 + 2 * tg;
                #pragma unroll
                for (int ni = 0; ni < 8; ni++) {
                    float2 bv = *(const float2*)(bp + ni * 8);
                    s[ni][2*p]   += bv.x;
                    s[ni][2*p+1] += bv.y;
                    mx[p] = fmaxf(mx[p], fmaxf(s[ni][2*p], s[ni][2*p+1]));
                }
            }
            float corr[2];
            #pragma unroll
            for (int p = 0; p < 2; p++) {
                mx[p] = fmaxf(mx[p], __shfl_xor_sync(0xffffffffu, mx[p], 1));
                mx[p] = fmaxf(mx[p], __shfl_xor_sync(0xffffffffu, mx[p], 2));
                float mnew = fmaxf(m_r[p], mx[p]);
                corr[p] = __expf(m_r[p] - mnew);
                m_r[p] = mnew;
                l_r[p] *= corr[p];
            }
            #pragma unroll
            for (int ni = 0; ni < 4; ni++) {
                o[ni][0] *= corr[0]; o[ni][1] *= corr[0];
                o[ni][2] *= corr[1]; o[ni][3] *= corr[1];
            }
            // ---- exp + P store + row sum (P rows are warp-private) ----
            float rsum[2] = {0.f, 0.f};
            #pragma unroll
            for (int p = 0; p < 2; p++) {
                int rloc = tm + p * 8 + g;
                #pragma unroll
                for (int ni = 0; ni < 8; ni++) {
                    float p0 = __expf(s[ni][2*p]   - m_r[p]);
                    float p1 = __expf(s[ni][2*p+1] - m_r[p]);
                    rsum[p] += p0 + p1;
                    P_s[rloc * LDK + PERM(ni * 4 + tg)] = pk(p0, p1);
                }
            }
            #pragma unroll
            for (int p = 0; p < 2; p++) {
                rsum[p] += __shfl_xor_sync(0xffffffffu, rsum[p], 1);
                rsum[p] += __shfl_xor_sync(0xffffffffu, rsum[p], 2);
                l_r[p] += rsum[p];
            }
            __syncwarp();
            __syncthreads();  // all warps past prev PV (Vnxt writable); Vcur visible
            if (j < 3) {
                #pragma unroll
                for (int ii = 0; ii < 4; ii++) {
                    int idx = ii * 256 + t;
                    int mp = idx >> 5, d = idx & 31;
                    Vnxt[d * LDK + PERM(mp)] = pk(vr[ii].x, vr[ii].y);
                }
            }
            // ---- O += P @ V ----
            #pragma unroll
            for (int ks = 0; ks < 4; ks++) {
                int off = 8 * ks + 2 * tg;
                uint2 xa = *(const uint2*)(P_s + (tm + g) * LDK + off);
                uint2 ya = *(const uint2*)(P_s + (tm + 8 + g) * LDK + off);
                uint32_t a[4] = {xa.x, ya.x, xa.y, ya.y};
                #pragma unroll
                for (int ni = 0; ni < 4; ni++) {
                    uint2 bv = *(const uint2*)(Vcur + (ni * 8 + g) * LDK + off);
                    bmma(o[ni], a, bv.x, bv.y);
                }
            }
        }
        // ---- normalize, write O_s pair-cols [h*16 .. h*16+16) ----
        float rinv[2] = {1.f / l_r[0], 1.f / l_r[1]};
        #pragma unroll
        for (int p = 0; p < 2; p++) {
            int rloc = tm + p * 8 + g;
            #pragma unroll
            for (int ni = 0; ni < 4; ni++)
                O_s[rloc * LDW + h * 16 + PERM(ni * 4 + tg)] =
                    pk(o[ni][2*p] * rinv[p], o[ni][2*p+1] * rinv[p]);
        }
    }

    // ---- proj + residual ----
    __syncthreads();
    for (int idx = t; idx < 96 * 12; idx += 256) {
        int r = idx / 12, c4 = idx % 12;
        cp_async16(&Ws[r * LDW + c4 * 4], &gw_proj[r * 48 + c4 * 4]);
    }
    CP_COMMIT;
    CP_WAIT0;
    __syncthreads();

    float acc[12][4];
    #pragma unroll
    for (int ni = 0; ni < 12; ni++)
        acc[ni][0] = acc[ni][1] = acc[ni][2] = acc[ni][3] = 0.f;
    bgemm16<12, 6, LDW, LDW>(O_s, Ws, acc, tm, lane);

    #pragma unroll
    for (int ni = 0; ni < 12; ni++) {
        int cn = ni * 8 + 2 * tg;
        float b0v = proj_b[cn], b1v = proj_b[cn + 1];
        #pragma unroll
        for (int p = 0; p < 2; p++) {
            int row = half * 128 + tm + p * 8 + g;
            float* tp = &g_t[((size_t)w * NTOK + row) * CH + cn];
            float2 pr = *(float2*)tp;
            pr.x += acc[ni][2*p]   + b0v;
            pr.y += acc[ni][2*p+1] + b1v;
            *(float2*)tp = pr;
        }
    }
    (void)vmp; (void)vd;
}

// ---------------------------------------------------------------------------
// K3: fused MLP: LN2 + fc1 + GELU + fc2 + residual, 128 tokens/CTA
// ---------------------------------------------------------------------------
__global__ __launch_bounds__(256, 2) void mlp_kernel(const float* __restrict__ ln_g,
                                                     const float* __restrict__ ln_b,
                                                     const float* __restrict__ fc1_b,
                                                     const float* __restrict__ fc2_b,
                                                     float* __restrict__ out) {
    extern __shared__ uint32_t sm[];
    uint32_t* As  = sm;               // [128][LDW]
    uint32_t* Hs  = sm + 7168;
    uint32_t* Wb0 = sm + 14336;
    uint32_t* Wb1 = sm + 14336 + 96 * LDW;
    int bw = blockIdx.x, w = bw >> 1, half = bw & 1;
    int t = threadIdx.x, lane = t & 31, wid = t >> 5, tm = wid * 16;
    int g = lane >> 2, tg = lane & 3;

    for (int idx = t; idx < 96 * 12; idx += 256) {
        int r = idx / 12, c4 = idx % 12;
        cp_async16(&Wb0[r * LDW + c4 * 4], &gw_fc1[r * 48 + c4 * 4]);
    }
    CP_COMMIT;

    if (t < 128) {
        int tok = half * 128 + t;
        const float4* tp = (const float4*)(g_t + ((size_t)w * NTOK + tok) * CH);
        float row[96];
        float sum = 0.f, sq = 0.f;
        #pragma unroll
        for (int c4 = 0; c4 < 24; c4++) {
            float4 v = tp[c4];
            row[4*c4] = v.x; row[4*c4+1] = v.y; row[4*c4+2] = v.z; row[4*c4+3] = v.w;
            sum += v.x + v.y + v.z + v.w;
            sq  += v.x*v.x + v.y*v.y + v.z*v.z + v.w*v.w;
        }
        float mean = sum * (1.f / CH);
        float rstd = rsqrtf(sq * (1.f / CH) - mean * mean + 1e-5f);
        #pragma unroll
        for (int p = 0; p < 48; p++) {
            float n0 = (row[2*p]   - mean) * rstd * __ldg(ln_g + 2*p)   + __ldg(ln_b + 2*p);
            float n1 = (row[2*p+1] - mean) * rstd * __ldg(ln_g + 2*p+1) + __ldg(ln_b + 2*p+1);
            As[t * LDW + PERM(p)] = pk(n0, n1);
        }
    }

    float acc2[12][4];
    #pragma unroll
    for (int ni = 0; ni < 12; ni++)
        acc2[ni][0] = acc2[ni][1] = acc2[ni][2] = acc2[ni][3] = 0.f;

    for (int c = 0; c < 4; c++) {
        CP_WAIT0;
        __syncthreads();
        for (int idx = t; idx < 96 * 12; idx += 256) {
            int r = idx / 12, c4 = idx % 12;
            cp_async16(&Wb1[r * LDW + c4 * 4], &gw_fc2[r * 192 + c * 48 + c4 * 4]);
        }
        CP_COMMIT;

        float acc1[12][4];
        #pragma unroll
        for (int ni = 0; ni < 12; ni++)
            acc1[ni][0] = acc1[ni][1] = acc1[ni][2] = acc1[ni][3] = 0.f;
        bgemm16<12, 6, LDW, LDW>(As, Wb0, acc1, tm, lane);

        #pragma unroll
        for (int ni = 0; ni < 12; ni++) {
            int cn = ni * 8 + 2 * tg;
            float b0v = fc1_b[c * CH + cn], b1v = fc1_b[c * CH + cn + 1];
            #pragma unroll
            for (int p = 0; p < 2; p++) {
                int rloc = tm + p * 8 + g;
                float v0 = acc1[ni][2*p]   + b0v;
                float v1 = acc1[ni][2*p+1] + b1v;
                float g0 = 0.5f * v0 * (1.f + erff(v0 * 0.70710678118654752f));
                float g1 = 0.5f * v1 * (1.f + erff(v1 * 0.70710678118654752f));
                Hs[rloc * LDW + PERM(ni * 4 + tg)] = pk(g0, g1);
            }
        }
        CP_WAIT0;
        __syncthreads();
        if (c < 3) {
            for (int idx = t; idx < 96 * 12; idx += 256) {
                int r = idx / 12, c4 = idx % 12;
                cp_async16(&Wb0[r * LDW + c4 * 4], &gw_fc1[((c + 1) * 96 + r) * 48 + c4 * 4]);
            }
            CP_COMMIT;
        }
        bgemm16<12, 6, LDW, LDW>(Hs, Wb1, acc2, tm, lane);
    }

    #pragma unroll
    for (int ni = 0; ni < 12; ni++) {
        int cn = ni * 8 + 2 * tg;
        float b0v = fc2_b[cn], b1v = fc2_b[cn + 1];
        #pragma unroll
        for (int p = 0; p < 2; p++) {
            int row = half * 128 + tm + p * 8 + g;
            const float2 tr = *(const float2*)&g_t[((size_t)w * NTOK + row) * CH + cn];
            float2 v = make_float2(acc2[ni][2*p]   + b0v + tr.x,
                                   acc2[ni][2*p+1] + b1v + tr.y);
            *(float2*)&out[((size_t)w * NTOK + row) * CH + cn] = v;
        }
    }
}

// ---------------------------------------------------------------------------
extern "C" void kernel_launch(void* const* d_in, const int* in_sizes, int n_in,
                              void* d_out, int out_size) {
    (void)in_sizes; (void)n_in; (void)out_size;
    const float* x      = (const float*)d_in[0];
    const float* qkv_w  = (const float*)d_in[1];
    const float* qkv_b  = (const float*)d_in[2];
    const float* proj_w = (const float*)d_in[3];
    const float* proj_b = (const float*)d_in[4];
    const float* btab   = (const float*)d_in[5];
    const float* ln1_g  = (const float*)d_in[6];
    const float* ln1_b  = (const float*)d_in[7];
    const float* ln2_g  = (const float*)d_in[8];
    const float* ln2_b  = (const float*)d_in[9];
    const float* fc1_w  = (const float*)d_in[10];
    const float* fc1_b  = (const float*)d_in[11];
    const float* fc2_w  = (const float*)d_in[12];
    const float* fc2_b  = (const float*)d_in[13];
    float* out = (float*)d_out;

    const int smem_qkv  = (128 * LDW + 2 * 96 * LDW) * 4;                 // 71680 B
    const int smem_attn = (7168 + 5120 + 10240 + 2 * 1280) * 4;          // 100352 B
    const int smem_mlp  = (2 * 128 * LDW + 2 * 96 * LDW) * 4;            // 100352 B
    cudaFuncSetAttribute(qkv_kernel,  cudaFuncAttributeMaxDynamicSharedMemorySize, smem_qkv);
    cudaFuncSetAttribute(attn_kernel, cudaFuncAttributeMaxDynamicSharedMemorySize, smem_attn);
    cudaFuncSetAttribute(mlp_kernel,  cudaFuncAttributeMaxDynamicSharedMemorySize, smem_mlp);

    prep_kernel<<<216, 256>>>(qkv_w, proj_w, fc1_w, fc2_w);
    bias_kernel<<<NH * NTOK, NTOK>>>(btab);
    qkv_kernel<<<NWIN * 2, 256, smem_qkv>>>(x, qkv_b, ln1_g, ln1_b);
    attn_kernel<<<NWIN * 2, 256, smem_attn>>>(proj_b);
    mlp_kernel<<<NWIN * 2, 256, smem_mlp>>>(ln2_g, ln2_b, fc1_b, fc2_b, out);
}

// round 7
// speedup vs baseline: 5.6235x; 1.1141x over previous
#include <cuda_runtime.h>
#include <cuda_bf16.h>
#include <math.h>
#include <stdint.h>

#define NWIN 512
#define NTOK 256
#define CH   96
#define NH   3
#define HD   32
#define HID  384
#define LDW  52    // stride (uint32) for 48-word operand rows (GEMM A/B, O_s)
#define LDV  20    // stride (uint32) for 16-word rows (K_s, V_s, P_s)
#define LOG2E 1.4426950408889634f

// Scratch (device globals)
__device__ float         g_t[(size_t)NWIN * NTOK * CH];       // residual fp32 [w][t][c]
__device__ __nv_bfloat16 g_q[(size_t)NWIN * NH * NTOK * HD];  // [t][d] plain, pre-scaled
__device__ __nv_bfloat16 g_k[(size_t)NWIN * NH * NTOK * HD];  // [t][d] plain
__device__ __nv_bfloat16 g_v[(size_t)NWIN * NH * NTOK * HD];  // [t][d] plain
__device__ uint32_t      g_biasp[NH * NTOK * 128];            // bf16x2 [h][m][n/2], *log2e
// weights as bf16x2 pairs, plain rows
__device__ uint32_t gw_qkv[288 * 48];
__device__ uint32_t gw_proj[96 * 48];
__device__ uint32_t gw_fc1[384 * 48];
__device__ uint32_t gw_fc2[96 * 192];

// ---------------------------------------------------------------------------
__device__ __forceinline__ void cp_async16(void* s, const void* g) {
    uint32_t sa = (uint32_t)__cvta_generic_to_shared(s);
    asm volatile("cp.async.cg.shared.global [%0], [%1], 16;" :: "r"(sa), "l"(g));
}
#define CP_COMMIT asm volatile("cp.async.commit_group;")
#define CP_WAIT0  asm volatile("cp.async.wait_group 0;")

__device__ __forceinline__ uint32_t s2u(const void* p) {
    return (uint32_t)__cvta_generic_to_shared(p);
}
__device__ __forceinline__ uint32_t pk(float a, float b) {
    __nv_bfloat162 h = __floats2bfloat162_rn(a, b);
    return *(uint32_t*)&h;
}
__device__ __forceinline__ float ex2(float x) {
    float y;
    asm("ex2.approx.ftz.f32 %0, %1;" : "=f"(y) : "f"(x));
    return y;
}
__device__ __forceinline__ void bmma(float* c, const uint32_t* a, uint32_t b0, uint32_t b1) {
    asm("mma.sync.aligned.m16n8k16.row.col.f32.bf16.bf16.f32 "
        "{%0,%1,%2,%3},{%4,%5,%6,%7},{%8,%9},{%0,%1,%2,%3};"
        : "+f"(c[0]), "+f"(c[1]), "+f"(c[2]), "+f"(c[3])
        : "r"(a[0]), "r"(a[1]), "r"(a[2]), "r"(a[3]), "r"(b0), "r"(b1));
}
__device__ __forceinline__ void ldsm4(uint32_t* r, uint32_t a) {
    asm volatile("ldmatrix.sync.aligned.m8n8.x4.shared.b16 {%0,%1,%2,%3},[%4];"
        : "=r"(r[0]), "=r"(r[1]), "=r"(r[2]), "=r"(r[3]) : "r"(a));
}
__device__ __forceinline__ void ldsm4t(uint32_t* r, uint32_t a) {
    asm volatile("ldmatrix.sync.aligned.m8n8.x4.trans.shared.b16 {%0,%1,%2,%3},[%4];"
        : "=r"(r[0]), "=r"(r[1]), "=r"(r[2]), "=r"(r[3]) : "r"(a));
}

// 16 rows x NT*8 cols over KS*16 k; both operands plain layout, stride LDW.
template <int NT, int KS>
__device__ __forceinline__ void bgemm(const uint32_t* __restrict__ As,
                                      const uint32_t* __restrict__ Ws,
                                      float acc[NT][4], int tm, int l) {
    uint32_t aAddr = s2u(As) + ((tm + (l & 7) + ((l >> 3) & 1) * 8) * LDW + ((l >> 4) & 1) * 4) * 4;
    uint32_t bAddr = s2u(Ws) + (((l & 7) + ((l >> 4) & 1) * 8) * LDW + ((l >> 3) & 1) * 4) * 4;
    #pragma unroll
    for (int ks = 0; ks < KS; ks++) {
        uint32_t a[4];
        ldsm4(a, aAddr + ks * 32);
        #pragma unroll
        for (int nq = 0; nq < NT / 2; nq++) {
            uint32_t b[4];
            ldsm4(b, bAddr + (nq * 16 * LDW) * 4 + ks * 32);
            bmma(acc[2 * nq],     a, b[0], b[1]);
            bmma(acc[2 * nq + 1], a, b[2], b[3]);
        }
    }
}

// ---------------------------------------------------------------------------
// K0a: weights -> bf16x2 pairs (plain)
// ---------------------------------------------------------------------------
__global__ void prep_kernel(const float* __restrict__ qkv_w, const float* __restrict__ proj_w,
                            const float* __restrict__ fc1_w, const float* __restrict__ fc2_w) {
    int i = blockIdx.x * 256 + threadIdx.x;
    if (i < 13824) {
        int r = i / 48, p = i % 48;
        gw_qkv[i] = pk(qkv_w[r * 96 + 2 * p], qkv_w[r * 96 + 2 * p + 1]);
        return;
    }
    i -= 13824;
    if (i < 4608) {
        int r = i / 48, p = i % 48;
        gw_proj[i] = pk(proj_w[r * 96 + 2 * p], proj_w[r * 96 + 2 * p + 1]);
        return;
    }
    i -= 4608;
    if (i < 18432) {
        int r = i / 48, p = i % 48;
        gw_fc1[i] = pk(fc1_w[r * 96 + 2 * p], fc1_w[r * 96 + 2 * p + 1]);
        return;
    }
    i -= 18432;
    if (i < 18432) {
        int r = i / 192, p = i % 192;
        gw_fc2[i] = pk(fc2_w[r * 384 + 2 * p], fc2_w[r * 384 + 2 * p + 1]);
    }
}

// ---------------------------------------------------------------------------
// K0b: gather relative-position bias -> bf16x2 [h][m][n/2], scaled by log2e
// ---------------------------------------------------------------------------
__global__ void bias_kernel(const float* __restrict__ bias_table) {
    int m = blockIdx.x & 255;
    int h = blockIdx.x >> 8;
    int n2 = threadIdx.x;          // 128 threads: pair of columns
    int n0 = 2 * n2, n1 = 2 * n2 + 1;
    int dy0 = (n0 >> 4) - (m >> 4), dx0 = (n0 & 15) - (m & 15);
    int dy1 = (n1 >> 4) - (m >> 4), dx1 = (n1 & 15) - (m & 15);
    float b0 = bias_table[((dy0 + 15) * 31 + (dx0 + 15)) * NH + h] * LOG2E;
    float b1 = bias_table[((dy1 + 15) * 31 + (dx1 + 15)) * NH + h] * LOG2E;
    g_biasp[(h * NTOK + m) * 128 + n2] = pk(b0, b1);
}

// ---------------------------------------------------------------------------
// K1: window partition + LN1 + QKV GEMM, 128 tokens/CTA
// ---------------------------------------------------------------------------
__global__ __launch_bounds__(256, 2) void qkv_kernel(const float* __restrict__ x,
                                                     const float* __restrict__ qkv_b,
                                                     const float* __restrict__ ln_g,
                                                     const float* __restrict__ ln_b) {
    extern __shared__ uint32_t sm[];
    uint32_t* As  = sm;               // [128][LDW]
    uint32_t* Wb0 = sm + 128 * LDW;
    uint32_t* Wb1 = Wb0 + 96 * LDW;
    int bw = blockIdx.x, w = bw >> 1, half = bw & 1;
    int t = threadIdx.x, l = t & 31, wid = t >> 5, tm = wid * 16;
    int g = l >> 2, tg = l & 3;
    int b = w >> 8, hb = (w >> 4) & 15, wb = w & 15;

    for (int idx = t; idx < 96 * 12; idx += 256) {
        int r = idx / 12, c4 = idx % 12;
        cp_async16(&Wb0[r * LDW + c4 * 4], &gw_qkv[r * 48 + c4 * 4]);
    }
    CP_COMMIT;

    if (t < 128) {
        int tok = half * 128 + t;
        int d = tok >> 6, ii = (tok >> 3) & 7, jj = tok & 7;
        const float* xp = x + ((size_t)b * CH * 4 + d) * 16384 + (hb * 8 + ii) * 128 + (wb * 8 + jj);
        float row[96];
        float sum = 0.f, sq = 0.f;
        float* gt = g_t + ((size_t)w * NTOK + tok) * CH;
        #pragma unroll 4
        for (int c = 0; c < CH; c++) {
            float v = xp[(size_t)c * 65536];
            sum += v; sq += v * v;
            row[c] = v;
            gt[c] = v;
        }
        float mean = sum * (1.f / CH);
        float rstd = rsqrtf(sq * (1.f / CH) - mean * mean + 1e-5f);
        #pragma unroll
        for (int p = 0; p < 48; p++) {
            float n0 = (row[2*p]   - mean) * rstd * __ldg(ln_g + 2*p)   + __ldg(ln_b + 2*p);
            float n1 = (row[2*p+1] - mean) * rstd * __ldg(ln_g + 2*p+1) + __ldg(ln_b + 2*p+1);
            As[t * LDW + p] = pk(n0, n1);
        }
    }

    const float QS = 0.17677669529663687f * LOG2E;  // hd^-0.5 * log2(e)
    for (int chunk = 0; chunk < 3; chunk++) {
        uint32_t* Wc = (chunk & 1) ? Wb1 : Wb0;
        uint32_t* Wn = (chunk & 1) ? Wb0 : Wb1;
        CP_WAIT0;
        __syncthreads();
        if (chunk < 2) {
            for (int idx = t; idx < 96 * 12; idx += 256) {
                int r = idx / 12, c4 = idx % 12;
                cp_async16(&Wn[r * LDW + c4 * 4], &gw_qkv[((chunk + 1) * 96 + r) * 48 + c4 * 4]);
            }
            CP_COMMIT;
        }
        float acc[12][4];
        #pragma unroll
        for (int ni = 0; ni < 12; ni++)
            acc[ni][0] = acc[ni][1] = acc[ni][2] = acc[ni][3] = 0.f;
        bgemm<12, 6>(As, Wc, acc, tm, l);

        #pragma unroll
        for (int ni = 0; ni < 12; ni++) {
            int cn = ni * 8 + 2 * tg;
            int h = cn >> 5, dd = cn & 31;
            float b0v = qkv_b[chunk * CH + cn], b1v = qkv_b[chunk * CH + cn + 1];
            size_t base = ((size_t)(w * NH + h)) * NTOK;
            #pragma unroll
            for (int p = 0; p < 2; p++) {
                int row = half * 128 + tm + p * 8 + g;
                float v0 = acc[ni][2*p]   + b0v;
                float v1 = acc[ni][2*p+1] + b1v;
                uint32_t* dst = (chunk == 0) ? (uint32_t*)g_q
                              : (chunk == 1) ? (uint32_t*)g_k : (uint32_t*)g_v;
                float sc = (chunk == 0) ? QS : 1.f;
                dst[(base + row) * 16 + (dd >> 1)] = pk(v0 * sc, v1 * sc);
            }
        }
    }
}

// ---------------------------------------------------------------------------
// K2: fused attention (3 heads) + proj + residual; one CTA per 128 q-tokens
// smem words: O_s[128][52] | P_s[128][20] | K_s[256][20] | V_s[256][20]
// ---------------------------------------------------------------------------
__global__ __launch_bounds__(256, 2) void attn_kernel(const float* __restrict__ proj_b) {
    extern __shared__ uint32_t smu[];
    uint32_t* O_s = smu;             // 6656
    uint32_t* P_s = smu + 6656;      // 2560
    uint32_t* K_s = smu + 9216;      // 5120
    uint32_t* V_s = smu + 14336;     // 5120
    uint32_t* Ws  = smu + 9216;      // overlay (proj)
    int bw = blockIdx.x, w = bw >> 1, half = bw & 1;
    int t = threadIdx.x, l = t & 31, wid = t >> 5, tm = wid * 16;
    int g = l >> 2, tg = l & 3;

    // lane-constant ldmatrix base addresses
    uint32_t kAddr = s2u(K_s) + (((l & 7) + ((l >> 4) & 1) * 8) * LDV + ((l >> 3) & 1) * 4) * 4;
    uint32_t vAddr = s2u(V_s) + (((l & 7) + ((l >> 3) & 1) * 8) * LDV + ((l >> 4) & 1) * 4) * 4;
    uint32_t pAddr = s2u(P_s) + ((tm + (l & 7) + ((l >> 3) & 1) * 8) * LDV + ((l >> 4) & 1) * 4) * 4;

    for (int h = 0; h < NH; h++) {
        size_t hbo = ((size_t)(w * NH + h)) * NTOK * HD;

        __syncthreads();  // prior head's K_s/V_s reads complete
        for (int idx = t; idx < 1024; idx += 256) {
            int m = idx >> 2, c = idx & 3;
            cp_async16(&K_s[m * LDV + c * 4], &g_k[hbo + m * 32 + c * 8]);
        }
        for (int idx = t; idx < 1024; idx += 256) {
            int m = idx >> 2, c = idx & 3;
            cp_async16(&V_s[m * LDV + c * 4], &g_v[hbo + m * 32 + c * 8]);
        }
        CP_COMMIT;

        uint32_t qa[2][4];
        {
            const uint32_t* qp = (const uint32_t*)(g_q + hbo);
            int qrow = half * 128 + tm + g;
            #pragma unroll
            for (int ks = 0; ks < 2; ks++) {
                qa[ks][0] = qp[qrow * 16 + 8 * ks + tg];
                qa[ks][1] = qp[(qrow + 8) * 16 + 8 * ks + tg];
                qa[ks][2] = qp[qrow * 16 + 8 * ks + tg + 4];
                qa[ks][3] = qp[(qrow + 8) * 16 + 8 * ks + tg + 4];
            }
        }
        CP_WAIT0;
        __syncthreads();

        float m_r[2] = {-1e30f, -1e30f}, l_r[2] = {0.f, 0.f};
        float o[4][4];
        #pragma unroll
        for (int ni = 0; ni < 4; ni++)
            o[ni][0] = o[ni][1] = o[ni][2] = o[ni][3] = 0.f;

        for (int j = 0; j < 4; j++) {
            // ---- S = Q K^T (16 x 64), log2-domain logits ----
            float s[8][4];
            #pragma unroll
            for (int ni = 0; ni < 8; ni++)
                s[ni][0] = s[ni][1] = s[ni][2] = s[ni][3] = 0.f;
            #pragma unroll
            for (int np = 0; np < 4; np++)
                #pragma unroll
                for (int ks = 0; ks < 2; ks++) {
                    uint32_t bq[4];
                    ldsm4(bq, kAddr + ((j * 64 + np * 16) * LDV + ks * 8) * 4);
                    bmma(s[2 * np],     qa[ks], bq[0], bq[1]);
                    bmma(s[2 * np + 1], qa[ks], bq[2], bq[3]);
                }
            // ---- bias + row max ----
            float mx[2] = {-1e30f, -1e30f};
            #pragma unroll
            for (int p = 0; p < 2; p++) {
                int row = half * 128 + tm + p * 8 + g;
                const uint32_t* bp = g_biasp + (h * NTOK + row) * 128 + j * 32 + tg;
                #pragma unroll
                for (int ni = 0; ni < 8; ni++) {
                    float2 bv = __bfloat1622float2(*(const __nv_bfloat162*)&bp[ni * 4]);
                    s[ni][2*p]   += bv.x;
                    s[ni][2*p+1] += bv.y;
                    mx[p] = fmaxf(mx[p], fmaxf(s[ni][2*p], s[ni][2*p+1]));
                }
            }
            float corr[2];
            #pragma unroll
            for (int p = 0; p < 2; p++) {
                mx[p] = fmaxf(mx[p], __shfl_xor_sync(0xffffffffu, mx[p], 1));
                mx[p] = fmaxf(mx[p], __shfl_xor_sync(0xffffffffu, mx[p], 2));
                float mnew = fmaxf(m_r[p], mx[p]);
                corr[p] = ex2(m_r[p] - mnew);
                m_r[p] = mnew;
                l_r[p] *= corr[p];
            }
            #pragma unroll
            for (int ni = 0; ni < 4; ni++) {
                o[ni][0] *= corr[0]; o[ni][1] *= corr[0];
                o[ni][2] *= corr[1]; o[ni][3] *= corr[1];
            }
            // ---- exp2 + P store + row sum (warp-private rows) ----
            float rsum[2] = {0.f, 0.f};
            #pragma unroll
            for (int p = 0; p < 2; p++) {
                int rloc = tm + p * 8 + g;
                #pragma unroll
                for (int ni = 0; ni < 8; ni++) {
                    float p0 = ex2(s[ni][2*p]   - m_r[p]);
                    float p1 = ex2(s[ni][2*p+1] - m_r[p]);
                    rsum[p] += p0 + p1;
                    P_s[rloc * LDV + ni * 4 + tg] = pk(p0, p1);
                }
            }
            #pragma unroll
            for (int p = 0; p < 2; p++) {
                rsum[p] += __shfl_xor_sync(0xffffffffu, rsum[p], 1);
                rsum[p] += __shfl_xor_sync(0xffffffffu, rsum[p], 2);
                l_r[p] += rsum[p];
            }
            __syncwarp();
            // ---- O += P @ V (A via ldsm, B via ldsm.trans) ----
            #pragma unroll
            for (int ks = 0; ks < 4; ks++) {
                uint32_t a[4];
                ldsm4(a, pAddr + ks * 32);
                #pragma unroll
                for (int nq = 0; nq < 2; nq++) {
                    uint32_t bv[4];
                    ldsm4t(bv, vAddr + ((j * 64 + ks * 16) * LDV + nq * 8) * 4);
                    bmma(o[2 * nq],     a, bv[0], bv[1]);
                    bmma(o[2 * nq + 1], a, bv[2], bv[3]);
                }
            }
            __syncwarp();  // P_s reads done before next j overwrites
        }
        // ---- normalize, write O_s word-cols [h*16 .. h*16+16) ----
        float rinv[2] = {1.f / l_r[0], 1.f / l_r[1]};
        #pragma unroll
        for (int p = 0; p < 2; p++) {
            int rloc = tm + p * 8 + g;
            #pragma unroll
            for (int ni = 0; ni < 4; ni++)
                O_s[rloc * LDW + h * 16 + ni * 4 + tg] =
                    pk(o[ni][2*p] * rinv[p], o[ni][2*p+1] * rinv[p]);
        }
    }

    // ---- proj + residual ----
    __syncthreads();  // last head's K/V reads done; overlay safe
    for (int idx = t; idx < 96 * 12; idx += 256) {
        int r = idx / 12, c4 = idx % 12;
        cp_async16(&Ws[r * LDW + c4 * 4], &gw_proj[r * 48 + c4 * 4]);
    }
    CP_COMMIT;
    CP_WAIT0;
    __syncthreads();

    float acc[12][4];
    #pragma unroll
    for (int ni = 0; ni < 12; ni++)
        acc[ni][0] = acc[ni][1] = acc[ni][2] = acc[ni][3] = 0.f;
    bgemm<12, 6>(O_s, Ws, acc, tm, l);

    #pragma unroll
    for (int ni = 0; ni < 12; ni++) {
        int cn = ni * 8 + 2 * tg;
        float b0v = proj_b[cn], b1v = proj_b[cn + 1];
        #pragma unroll
        for (int p = 0; p < 2; p++) {
            int row = half * 128 + tm + p * 8 + g;
            float* tp = &g_t[((size_t)w * NTOK + row) * CH + cn];
            float2 pr = *(float2*)tp;
            pr.x += acc[ni][2*p]   + b0v;
            pr.y += acc[ni][2*p+1] + b1v;
            *(float2*)tp = pr;
        }
    }
}

// ---------------------------------------------------------------------------
// K3: fused MLP: LN2 + fc1 + GELU + fc2 + residual, 128 tokens/CTA
// ---------------------------------------------------------------------------
__global__ __launch_bounds__(256, 2) void mlp_kernel(const float* __restrict__ ln_g,
                                                     const float* __restrict__ ln_b,
                                                     const float* __restrict__ fc1_b,
                                                     const float* __restrict__ fc2_b,
                                                     float* __restrict__ out) {
    extern __shared__ uint32_t sm[];
    uint32_t* As  = sm;               // [128][LDW]
    uint32_t* Hs  = sm + 128 * LDW;
    uint32_t* Wb0 = sm + 2 * 128 * LDW;
    uint32_t* Wb1 = Wb0 + 96 * LDW;
    int bw = blockIdx.x, w = bw >> 1, half = bw & 1;
    int t = threadIdx.x, l = t & 31, wid = t >> 5, tm = wid * 16;
    int g = l >> 2, tg = l & 3;

    for (int idx = t; idx < 96 * 12; idx += 256) {
        int r = idx / 12, c4 = idx % 12;
        cp_async16(&Wb0[r * LDW + c4 * 4], &gw_fc1[r * 48 + c4 * 4]);
    }
    CP_COMMIT;

    if (t < 128) {
        int tok = half * 128 + t;
        const float4* tp = (const float4*)(g_t + ((size_t)w * NTOK + tok) * CH);
        float row[96];
        float sum = 0.f, sq = 0.f;
        #pragma unroll
        for (int c4 = 0; c4 < 24; c4++) {
            float4 v = tp[c4];
            row[4*c4] = v.x; row[4*c4+1] = v.y; row[4*c4+2] = v.z; row[4*c4+3] = v.w;
            sum += v.x + v.y + v.z + v.w;
            sq  += v.x*v.x + v.y*v.y + v.z*v.z + v.w*v.w;
        }
        float mean = sum * (1.f / CH);
        float rstd = rsqrtf(sq * (1.f / CH) - mean * mean + 1e-5f);
        #pragma unroll
        for (int p = 0; p < 48; p++) {
            float n0 = (row[2*p]   - mean) * rstd * __ldg(ln_g + 2*p)   + __ldg(ln_b + 2*p);
            float n1 = (row[2*p+1] - mean) * rstd * __ldg(ln_g + 2*p+1) + __ldg(ln_b + 2*p+1);
            As[t * LDW + p] = pk(n0, n1);
        }
    }

    float acc2[12][4];
    #pragma unroll
    for (int ni = 0; ni < 12; ni++)
        acc2[ni][0] = acc2[ni][1] = acc2[ni][2] = acc2[ni][3] = 0.f;

    for (int c = 0; c < 4; c++) {
        CP_WAIT0;
        __syncthreads();
        for (int idx = t; idx < 96 * 12; idx += 256) {
            int r = idx / 12, c4 = idx % 12;
            cp_async16(&Wb1[r * LDW + c4 * 4], &gw_fc2[r * 192 + c * 48 + c4 * 4]);
        }
        CP_COMMIT;

        float acc1[12][4];
        #pragma unroll
        for (int ni = 0; ni < 12; ni++)
            acc1[ni][0] = acc1[ni][1] = acc1[ni][2] = acc1[ni][3] = 0.f;
        bgemm<12, 6>(As, Wb0, acc1, tm, l);

        #pragma unroll
        for (int ni = 0; ni < 12; ni++) {
            int cn = ni * 8 + 2 * tg;
            float b0v = fc1_b[c * CH + cn], b1v = fc1_b[c * CH + cn + 1];
            #pragma unroll
            for (int p = 0; p < 2; p++) {
                int rloc = tm + p * 8 + g;
                float v0 = acc1[ni][2*p]   + b0v;
                float v1 = acc1[ni][2*p+1] + b1v;
                float g0 = 0.5f * v0 * (1.f + erff(v0 * 0.70710678118654752f));
                float g1 = 0.5f * v1 * (1.f + erff(v1 * 0.70710678118654752f));
                Hs[rloc * LDW + ni * 4 + tg] = pk(g0, g1);
            }
        }
        CP_WAIT0;
        __syncthreads();
        if (c < 3) {
            for (int idx = t; idx < 96 * 12; idx += 256) {
                int r = idx / 12, c4 = idx % 12;
                cp_async16(&Wb0[r * LDW + c4 * 4], &gw_fc1[((c + 1) * 96 + r) * 48 + c4 * 4]);
            }
            CP_COMMIT;
        }
        bgemm<12, 6>(Hs, Wb1, acc2, tm, l);
    }

    #pragma unroll
    for (int ni = 0; ni < 12; ni++) {
        int cn = ni * 8 + 2 * tg;
        float b0v = fc2_b[cn], b1v = fc2_b[cn + 1];
        #pragma unroll
        for (int p = 0; p < 2; p++) {
            int row = half * 128 + tm + p * 8 + g;
            const float2 tr = *(const float2*)&g_t[((size_t)w * NTOK + row) * CH + cn];
            float2 v = make_float2(acc2[ni][2*p]   + b0v + tr.x,
                                   acc2[ni][2*p+1] + b1v + tr.y);
            *(float2*)&out[((size_t)w * NTOK + row) * CH + cn] = v;
        }
    }
}

// ---------------------------------------------------------------------------
extern "C" void kernel_launch(void* const* d_in, const int* in_sizes, int n_in,
                              void* d_out, int out_size) {
    (void)in_sizes; (void)n_in; (void)out_size;
    const float* x      = (const float*)d_in[0];
    const float* qkv_w  = (const float*)d_in[1];
    const float* qkv_b  = (const float*)d_in[2];
    const float* proj_w = (const float*)d_in[3];
    const float* proj_b = (const float*)d_in[4];
    const float* btab   = (const float*)d_in[5];
    const float* ln1_g  = (const float*)d_in[6];
    const float* ln1_b  = (const float*)d_in[7];
    const float* ln2_g  = (const float*)d_in[8];
    const float* ln2_b  = (const float*)d_in[9];
    const float* fc1_w  = (const float*)d_in[10];
    const float* fc1_b  = (const float*)d_in[11];
    const float* fc2_w  = (const float*)d_in[12];
    const float* fc2_b  = (const float*)d_in[13];
    float* out = (float*)d_out;

    const int smem_qkv  = (128 * LDW + 2 * 96 * LDW) * 4;        // 66560 B
    const int smem_attn = (6656 + 2560 + 5120 + 5120) * 4;       // 77824 B
    const int smem_mlp  = (2 * 128 * LDW + 2 * 96 * LDW) * 4;    // 93184 B
    cudaFuncSetAttribute(qkv_kernel,  cudaFuncAttributeMaxDynamicSharedMemorySize, smem_qkv);
    cudaFuncSetAttribute(attn_kernel, cudaFuncAttributeMaxDynamicSharedMemorySize, smem_attn);
    cudaFuncSetAttribute(mlp_kernel,  cudaFuncAttributeMaxDynamicSharedMemorySize, smem_mlp);

    prep_kernel<<<216, 256>>>(qkv_w, proj_w, fc1_w, fc2_w);
    bias_kernel<<<NH * NTOK, 128>>>(btab);
    qkv_kernel<<<NWIN * 2, 256, smem_qkv>>>(x, qkv_b, ln1_g, ln1_b);
    attn_kernel<<<NWIN * 2, 256, smem_attn>>>(proj_b);
    mlp_kernel<<<NWIN * 2, 256, smem_mlp>>>(ln2_g, ln2_b, fc1_b, fc2_b, out);
}